// round 6
// baseline (speedup 1.0000x reference)
#include <cuda_runtime.h>
#include <math.h>

#define BATCH 2
#define SEQ   2048
#define DM    1024
#define NH    16
#define HD    64

// Scratch (static device globals -- no allocation APIs anywhere).
static __device__ float g_q[(size_t)BATCH * NH * SEQ * HD];   // [B,H,T,Dh]
static __device__ float g_k[(size_t)BATCH * NH * SEQ * HD];
static __device__ float g_v[(size_t)BATCH * NH * SEQ * HD];
static __device__ float g_att[(size_t)BATCH * SEQ * DM];      // [B,T,C]

// ---------------------------------------------------------------------------
// Double-buffered SGEMM: C[M,N] = A[M,K] @ B[K,N] + bias[N]
// Block tile 128x128, K-tile 8, 256 threads, 8x8 per-thread microtile.
// All dims are multiples of the tiles (M=4096, N in {3072,1024}, K=1024).
// MODE 1: QKV epilogue -> scatter into g_q/g_k/g_v head-major layouts.
// MODE 2: A is g_att (proj GEMM), plain write to C.
// ---------------------------------------------------------------------------
template<int MODE>
__global__ __launch_bounds__(256)
void sgemm_kernel(const float* __restrict__ Ain, const float* __restrict__ B,
                  const float* __restrict__ bias, float* __restrict__ C,
                  int M, int N, int K)
{
    const float* __restrict__ A = (MODE == 2) ? (const float*)g_att : Ain;

    __shared__ float As[2][8][128];
    __shared__ float Bs[2][8][128];

    const int tid = threadIdx.x;
    const int bm0 = blockIdx.y * 128;
    const int bn0 = blockIdx.x * 128;
    const int tx = tid & 15;   // N direction, 16 threads
    const int ty = tid >> 4;   // M direction, 16 threads

    // A tile load: 128 rows x 8 cols = 256 float4 (one per thread), transposed store.
    const int a_row = tid >> 1;
    const int a_k   = (tid & 1) * 4;
    // B tile load: 8 rows x 128 cols = 256 float4 (one per thread), direct store.
    const int b_k   = tid >> 5;
    const int b_col = (tid & 31) * 4;

    const float* Aptr = A + (size_t)(bm0 + a_row) * K + a_k;
    const float* Bptr = B + (size_t)b_k * N + bn0 + b_col;

    float4 av = *(const float4*)Aptr;
    float4 bv = *(const float4*)Bptr;
    As[0][a_k + 0][a_row] = av.x;
    As[0][a_k + 1][a_row] = av.y;
    As[0][a_k + 2][a_row] = av.z;
    As[0][a_k + 3][a_row] = av.w;
    *(float4*)&Bs[0][b_k][b_col] = bv;
    __syncthreads();

    float acc[8][8];
    #pragma unroll
    for (int i = 0; i < 8; ++i)
        #pragma unroll
        for (int j = 0; j < 8; ++j) acc[i][j] = 0.f;

    const int nt = K / 8;
    int buf = 0;
    for (int t = 0; t < nt; ++t) {
        if (t + 1 < nt) {
            av = *(const float4*)(Aptr + (t + 1) * 8);
            bv = *(const float4*)(Bptr + (size_t)(t + 1) * 8 * N);
        }
        #pragma unroll
        for (int kk = 0; kk < 8; ++kk) {
            float ar[8], br[8];
            *(float4*)&ar[0] = *(const float4*)&As[buf][kk][ty * 8];
            *(float4*)&ar[4] = *(const float4*)&As[buf][kk][ty * 8 + 4];
            *(float4*)&br[0] = *(const float4*)&Bs[buf][kk][tx * 8];
            *(float4*)&br[4] = *(const float4*)&Bs[buf][kk][tx * 8 + 4];
            #pragma unroll
            for (int i = 0; i < 8; ++i)
                #pragma unroll
                for (int j = 0; j < 8; ++j)
                    acc[i][j] += ar[i] * br[j];
        }
        if (t + 1 < nt) {
            buf ^= 1;
            As[buf][a_k + 0][a_row] = av.x;
            As[buf][a_k + 1][a_row] = av.y;
            As[buf][a_k + 2][a_row] = av.z;
            As[buf][a_k + 3][a_row] = av.w;
            *(float4*)&Bs[buf][b_k][b_col] = bv;
            __syncthreads();
        }
    }

    // Bias for this thread's 8 columns
    const int colbase = bn0 + tx * 8;
    float bs[8];
    *(float4*)&bs[0] = *(const float4*)&bias[colbase];
    *(float4*)&bs[4] = *(const float4*)&bias[colbase + 4];

    if (MODE == 1) {
        // colbase is 8-aligned -> the 8 columns never cross a 64 (head) or
        // 1024 (q/k/v) boundary.
        const int which = colbase / DM;          // 0=q,1=k,2=v
        const int cmod  = colbase % DM;
        const int h     = cmod / HD;
        const int d0    = cmod % HD;
        float* dst = (which == 0) ? g_q : (which == 1) ? g_k : g_v;
        #pragma unroll
        for (int i = 0; i < 8; ++i) {
            const int row = bm0 + ty * 8 + i;    // row = b*SEQ + t
            const int bb  = row >> 11;           // /2048
            const int tt  = row & (SEQ - 1);
            float* dp = dst + (((size_t)(bb * NH + h) * SEQ + tt) * HD + d0);
            float4 o0 = make_float4(acc[i][0] + bs[0], acc[i][1] + bs[1],
                                    acc[i][2] + bs[2], acc[i][3] + bs[3]);
            float4 o1 = make_float4(acc[i][4] + bs[4], acc[i][5] + bs[5],
                                    acc[i][6] + bs[6], acc[i][7] + bs[7]);
            *(float4*)(dp)     = o0;
            *(float4*)(dp + 4) = o1;
        }
    } else {
        #pragma unroll
        for (int i = 0; i < 8; ++i) {
            const int row = bm0 + ty * 8 + i;
            float* cp = C + (size_t)row * N + colbase;
            float4 o0 = make_float4(acc[i][0] + bs[0], acc[i][1] + bs[1],
                                    acc[i][2] + bs[2], acc[i][3] + bs[3]);
            float4 o1 = make_float4(acc[i][4] + bs[4], acc[i][5] + bs[5],
                                    acc[i][6] + bs[6], acc[i][7] + bs[7]);
            *(float4*)(cp)     = o0;
            *(float4*)(cp + 4) = o1;
        }
    }
}

// ---------------------------------------------------------------------------
// Flash attention (causal). One thread owns one Q row (q row + O accumulator
// in registers). K/V processed in 64-row smem tiles; all lanes read the same
// K/V element at a time -> pure broadcast LDS, conflict-free.
// Online softmax in 8-column chunks; the chunk loop is NOT unrolled so the
// hot body (~21 KB SASS) stays resident in the 32 KB I$ L1.5.
// grid = (SEQ/128, B*H), block = 128.
// ---------------------------------------------------------------------------
__global__ __launch_bounds__(128, 2)
void flash_kernel(float scale)
{
    __shared__ float Ks[64 * HD];
    __shared__ float Vs[64 * HD];

    const int bh   = blockIdx.y;                       // b*NH + h
    const int rt   = (gridDim.x - 1) - blockIdx.x;     // heavy tiles first
    const int row0 = rt * 128;
    const int tid  = threadIdx.x;
    const int row  = row0 + tid;                       // global t for this thread

    // Load q row into registers (pre-scaled so the score is just a dot product)
    const float* qp = g_q + ((size_t)bh * SEQ + row) * HD;
    float qr[HD];
    #pragma unroll
    for (int d = 0; d < HD; d += 4) {
        float4 q4 = *(const float4*)(qp + d);
        qr[d + 0] = q4.x * scale;
        qr[d + 1] = q4.y * scale;
        qr[d + 2] = q4.z * scale;
        qr[d + 3] = q4.w * scale;
    }

    float o[HD];
    #pragma unroll
    for (int d = 0; d < HD; ++d) o[d] = 0.f;
    float m = -1e30f, l = 0.f;

    const float* kbase = g_k + (size_t)bh * SEQ * HD;
    const float* vbase = g_v + (size_t)bh * SEQ * HD;
    const int ntile = (row0 + 128) / 64;

    for (int tIdx = 0; tIdx < ntile; ++tIdx) {
        const int c0 = tIdx * 64;
        __syncthreads();   // previous tile fully consumed
        // cooperative load: 64x64 floats = 1024 float4 per tile, 8 per thread
        #pragma unroll
        for (int u = 0; u < 8; ++u) {
            const int idx = (u * 128 + tid) * 4;       // float offset
            *(float4*)&Ks[idx] = *(const float4*)(kbase + (size_t)c0 * HD + idx);
            *(float4*)&Vs[idx] = *(const float4*)(vbase + (size_t)c0 * HD + idx);
        }
        __syncthreads();

        #pragma unroll 1
        for (int jc = 0; jc < 64; jc += 8) {
            float s[8];
            #pragma unroll
            for (int jj = 0; jj < 8; ++jj) {
                const float* kr = &Ks[(jc + jj) * HD];
                float a = 0.f;
                #pragma unroll
                for (int d = 0; d < HD; ++d) a += qr[d] * kr[d];
                const int col = c0 + jc + jj;
                s[jj] = (col <= row) ? a : -1e30f;
            }
            float cmax = s[0];
            #pragma unroll
            for (int jj = 1; jj < 8; ++jj) cmax = fmaxf(cmax, s[jj]);
            if (cmax > m) {
                const float alpha = __expf(m - cmax);
                m = cmax;
                l *= alpha;
                #pragma unroll
                for (int d = 0; d < HD; ++d) o[d] *= alpha;
            }
            #pragma unroll
            for (int jj = 0; jj < 8; ++jj) {
                const float p = __expf(s[jj] - m);
                l += p;
                const float* vr = &Vs[(jc + jj) * HD];
                #pragma unroll
                for (int d = 0; d < HD; ++d) o[d] += p * vr[d];
            }
        }
    }

    const float inv = 1.f / l;
    const int bb = bh >> 4;          // / NH
    const int h  = bh & (NH - 1);
    float* op = g_att + ((size_t)bb * SEQ + row) * DM + h * HD;
    #pragma unroll
    for (int d = 0; d < HD; d += 4) {
        float4 v4 = make_float4(o[d] * inv, o[d + 1] * inv,
                                o[d + 2] * inv, o[d + 3] * inv);
        *(float4*)(op + d) = v4;
    }
}

extern "C" void kernel_launch(void* const* d_in, const int* in_sizes, int n_in,
                              void* d_out, int out_size)
{
    const float* x      = (const float*)d_in[0];
    const float* w_qkv  = (const float*)d_in[1];
    const float* b_qkv  = (const float*)d_in[2];
    const float* w_proj = (const float*)d_in[3];
    const float* b_proj = (const float*)d_in[4];
    float* out = (float*)d_out;

    const int M = BATCH * SEQ;   // 4096

    // 1) QKV projection + scatter to head-major q/k/v
    {
        dim3 grid((3 * DM) / 128, M / 128);   // 24 x 32
        sgemm_kernel<1><<<grid, 256>>>(x, w_qkv, b_qkv, nullptr, M, 3 * DM, DM);
    }

    // 2) Causal flash attention -> g_att [B,T,C]
    {
        dim3 grid(SEQ / 128, BATCH * NH);     // 16 x 32
        const float scale = 0.125f;           // 1/sqrt(64)
        flash_kernel<<<grid, 128>>>(scale);
    }

    // 3) Output projection
    {
        dim3 grid(DM / 128, M / 128);         // 8 x 32
        sgemm_kernel<2><<<grid, 256>>>(nullptr, w_proj, b_proj, out, M, DM, DM);
    }
}

// round 12
// speedup vs baseline: 2.4349x; 2.4349x over previous
#include <cuda_runtime.h>
#include <cuda_bf16.h>
#include <cstdint>
#include <math.h>

#define BATCH 2
#define SEQ   2048
#define DM    1024
#define NH    16
#define HD    64
#define MTOT  (BATCH * SEQ)          // 4096

// ---------------- static scratch (no allocation APIs) ----------------------
static __device__ float g_q[(size_t)BATCH * NH * SEQ * HD];   // [B,H,T,Dh] fp32
static __device__ float g_k[(size_t)BATCH * NH * SEQ * HD];
static __device__ float g_v[(size_t)BATCH * NH * SEQ * HD];

static __device__ __nv_bfloat16 g_xhi[(size_t)MTOT * DM];     // x split  [M,K]
static __device__ __nv_bfloat16 g_xlo[(size_t)MTOT * DM];
static __device__ __nv_bfloat16 g_wqh[(size_t)3 * DM * DM];   // w_qkv^T  [N,K]
static __device__ __nv_bfloat16 g_wql[(size_t)3 * DM * DM];
static __device__ __nv_bfloat16 g_wph[(size_t)DM * DM];       // w_proj^T [N,K]
static __device__ __nv_bfloat16 g_wpl[(size_t)DM * DM];
static __device__ __nv_bfloat16 g_ahi[(size_t)MTOT * DM];     // attn out  [M,K]
static __device__ __nv_bfloat16 g_alo[(size_t)MTOT * DM];

// ---------------- helpers ---------------------------------------------------
__device__ __forceinline__ uint32_t smem_to_u32(const void* p) {
    uint32_t a;
    asm("{ .reg .u64 t; cvta.to.shared.u64 t, %1; cvt.u32.u64 %0, t; }" : "=r"(a) : "l"(p));
    return a;
}
__device__ __forceinline__ void cp_async16(uint32_t s, const void* g) {
    asm volatile("cp.async.cg.shared.global [%0], [%1], 16;" :: "r"(s), "l"(g) : "memory");
}
__device__ __forceinline__ void ldsm4(uint32_t* r, uint32_t a) {
    asm volatile("ldmatrix.sync.aligned.m8n8.x4.shared.b16 {%0,%1,%2,%3}, [%4];"
                 : "=r"(r[0]), "=r"(r[1]), "=r"(r[2]), "=r"(r[3]) : "r"(a));
}
__device__ __forceinline__ void ldsm2(uint32_t* r, uint32_t a) {
    asm volatile("ldmatrix.sync.aligned.m8n8.x2.shared.b16 {%0,%1}, [%2];"
                 : "=r"(r[0]), "=r"(r[1]) : "r"(a));
}
__device__ __forceinline__ void mma_bf16(float* c, const uint32_t* a, const uint32_t* b) {
    asm volatile(
        "mma.sync.aligned.m16n8k16.row.col.f32.bf16.bf16.f32 "
        "{%0,%1,%2,%3}, {%4,%5,%6,%7}, {%8,%9}, {%0,%1,%2,%3};"
        : "+f"(c[0]), "+f"(c[1]), "+f"(c[2]), "+f"(c[3])
        : "r"(a[0]), "r"(a[1]), "r"(a[2]), "r"(a[3]), "r"(b[0]), "r"(b[1]));
}
__device__ __forceinline__ void split_bf16(float v, __nv_bfloat16& h, __nv_bfloat16& l) {
    h = __float2bfloat16(v);
    l = __float2bfloat16(v - __bfloat162float(h));
}

// ---------------- prep kernels ---------------------------------------------
__global__ __launch_bounds__(256)
void conv_split_kernel(const float* __restrict__ src,
                       __nv_bfloat16* __restrict__ dhi, __nv_bfloat16* __restrict__ dlo)
{
    const size_t i = ((size_t)blockIdx.x * 256 + threadIdx.x) * 4;
    float4 v = *(const float4*)(src + i);
    __nv_bfloat16 h0, h1, h2, h3, l0, l1, l2, l3;
    split_bf16(v.x, h0, l0); split_bf16(v.y, h1, l1);
    split_bf16(v.z, h2, l2); split_bf16(v.w, h3, l3);
    __nv_bfloat162 ph0(h0, h1), ph1(h2, h3), pl0(l0, l1), pl1(l2, l3);
    uint2 uh = make_uint2(*(uint32_t*)&ph0, *(uint32_t*)&ph1);
    uint2 ul = make_uint2(*(uint32_t*)&pl0, *(uint32_t*)&pl1);
    *(uint2*)(dhi + i) = uh;
    *(uint2*)(dlo + i) = ul;
}

// Transpose + split: src fp32 [K,N] -> dst bf16 [N,K] hi/lo
__global__ __launch_bounds__(256)
void transpose_conv_kernel(const float* __restrict__ src,
                           __nv_bfloat16* __restrict__ dhi, __nv_bfloat16* __restrict__ dlo,
                           int K, int N)
{
    __shared__ float t[32][33];
    const int n0 = blockIdx.x * 32, k0 = blockIdx.y * 32;
    #pragma unroll
    for (int i = 0; i < 4; ++i)
        t[threadIdx.y + i * 8][threadIdx.x] =
            src[(size_t)(k0 + threadIdx.y + i * 8) * N + n0 + threadIdx.x];
    __syncthreads();
    #pragma unroll
    for (int i = 0; i < 4; ++i) {
        const int n = n0 + threadIdx.y + i * 8;
        const int k = k0 + threadIdx.x;
        __nv_bfloat16 h, l;
        split_bf16(t[threadIdx.x][threadIdx.y + i * 8], h, l);
        dhi[(size_t)n * K + k] = h;
        dlo[(size_t)n * K + k] = l;
    }
}

// ---------------- HMMA split-bf16 GEMM -------------------------------------
// C[128x128] = A[M,K] @ B^T, A/B K-major bf16 hi/lo; D = AhBh + AhBl + AlBh.
// 256 threads = 8 warps (2 M x 4 N), 64x32 per warp = 4x4 m16n8k16 tiles.
// Smem rows padded to 80B -> ldmatrix 8-row groups cover all 32 banks once.
#define TS_ROW   80u
#define TS_MAT   (128u * TS_ROW)     // 10240
#define TS_STAGE (4u * TS_MAT)       // 40960
#define TS_TOTAL (2u * TS_STAGE)     // 81920

template<int MODE>   // 1 = QKV scatter epilogue, 2 = plain C epilogue
__global__ __launch_bounds__(256)
void hmma_gemm(const __nv_bfloat16* __restrict__ Ahi, const __nv_bfloat16* __restrict__ Alo,
               const __nv_bfloat16* __restrict__ Bhi, const __nv_bfloat16* __restrict__ Blo,
               const float* __restrict__ bias, float* __restrict__ Cout, int Ncols, int K)
{
    extern __shared__ char smem[];
    const uint32_t sbase = smem_to_u32(smem);
    const int tid = threadIdx.x, lane = tid & 31, wid = tid >> 5;
    const int warp_m = wid & 1, warp_n = wid >> 1;
    const int bm0 = blockIdx.y * 128, bn0 = blockIdx.x * 128;

    // ---- async tile loader: 4 matrices x 128 rows x 4 x 16B = 2048 cp.async
    auto issue_stage = [&](int c, int stage) {
        const int k0 = c << 5;
        #pragma unroll
        for (int i = 0; i < 8; ++i) {
            const int lin  = i * 256 + tid;
            const int mat  = lin >> 9;
            const int rem  = lin & 511;
            const int row  = rem >> 2;
            const int unit = rem & 3;
            const __nv_bfloat16* src = (mat == 0) ? Ahi : (mat == 1) ? Alo
                                     : (mat == 2) ? Bhi : Blo;
            const int grow = ((mat < 2) ? bm0 : bn0) + row;
            const void* g = src + (size_t)grow * K + k0 + unit * 8;
            const uint32_t s = sbase + stage * TS_STAGE + mat * TS_MAT
                             + row * TS_ROW + unit * 16;
            cp_async16(s, g);
        }
        asm volatile("cp.async.commit_group;" ::: "memory");
    };

    float acc[4][4][4];
    #pragma unroll
    for (int mt = 0; mt < 4; ++mt)
        #pragma unroll
        for (int nt = 0; nt < 4; ++nt)
            #pragma unroll
            for (int e = 0; e < 4; ++e) acc[mt][nt][e] = 0.f;

    const int nchunk = K >> 5;
    issue_stage(0, 0);

    for (int c = 0; c < nchunk; ++c) {
        if (c + 1 < nchunk) {
            issue_stage(c + 1, (c + 1) & 1);
            asm volatile("cp.async.wait_group 1;" ::: "memory");
        } else {
            asm volatile("cp.async.wait_group 0;" ::: "memory");
        }
        __syncthreads();

        const uint32_t st = sbase + (uint32_t)(c & 1) * TS_STAGE;
        #pragma unroll
        for (int ks = 0; ks < 2; ++ks) {
            uint32_t ahi[4][4], alo[4][4], bhi[4][2], blo[4][2];
            const int arow = warp_m * 64 + (lane & 15);
            const uint32_t acol = (uint32_t)(ks * 32 + (lane >> 4) * 16);
            #pragma unroll
            for (int mt = 0; mt < 4; ++mt) {
                const uint32_t a = st + (uint32_t)(arow + mt * 16) * TS_ROW + acol;
                ldsm4(ahi[mt], a);
                ldsm4(alo[mt], a + TS_MAT);
            }
            const int brow = warp_n * 32 + ((lane & 15) & 7);
            const uint32_t bcol = (uint32_t)(ks * 32 + (((lane & 15) >> 3)) * 16);
            #pragma unroll
            for (int nt = 0; nt < 4; ++nt) {
                const uint32_t b = st + 2u * TS_MAT + (uint32_t)(brow + nt * 8) * TS_ROW + bcol;
                ldsm2(bhi[nt], b);
                ldsm2(blo[nt], b + TS_MAT);
            }
            #pragma unroll
            for (int mt = 0; mt < 4; ++mt)
                #pragma unroll
                for (int nt = 0; nt < 4; ++nt) {
                    mma_bf16(acc[mt][nt], ahi[mt], bhi[nt]);
                    mma_bf16(acc[mt][nt], ahi[mt], blo[nt]);
                    mma_bf16(acc[mt][nt], alo[mt], bhi[nt]);
                }
        }
        __syncthreads();
    }

    // ---- epilogue: c-frag lane map: row gid (+8), cols 2*tig, 2*tig+1
    const int gid = lane >> 2, tig = lane & 3;
    #pragma unroll
    for (int mt = 0; mt < 4; ++mt) {
        const int r1 = bm0 + warp_m * 64 + mt * 16 + gid;
        const int r2 = r1 + 8;
        #pragma unroll
        for (int nt = 0; nt < 4; ++nt) {
            const int col = bn0 + warp_n * 32 + nt * 8 + tig * 2;
            const float b0 = bias[col], b1 = bias[col + 1];
            float2 v1 = make_float2(acc[mt][nt][0] + b0, acc[mt][nt][1] + b1);
            float2 v2 = make_float2(acc[mt][nt][2] + b0, acc[mt][nt][3] + b1);
            if (MODE == 1) {
                const int which = col >> 10;
                const int hh = (col & (DM - 1)) >> 6;
                const int d0 = col & (HD - 1);
                float* dst = (which == 0) ? g_q : (which == 1) ? g_k : g_v;
                const int bb1 = r1 >> 11, tt1 = r1 & (SEQ - 1);
                const int bb2 = r2 >> 11, tt2 = r2 & (SEQ - 1);
                *(float2*)(dst + (((size_t)(bb1 * NH + hh) * SEQ + tt1) * HD + d0)) = v1;
                *(float2*)(dst + (((size_t)(bb2 * NH + hh) * SEQ + tt2) * HD + d0)) = v2;
            } else {
                *(float2*)(Cout + (size_t)r1 * Ncols + col) = v1;
                *(float2*)(Cout + (size_t)r2 * Ncols + col) = v2;
            }
        }
    }
}

// ---------------- flash attention (fp32, proven core) ----------------------
__global__ __launch_bounds__(128, 2)
void flash_kernel(float scale)
{
    __shared__ float Ks[64 * HD];
    __shared__ float Vs[64 * HD];

    const int bh   = blockIdx.y;
    const int rt   = (gridDim.x - 1) - blockIdx.x;     // heavy tiles first
    const int row0 = rt * 128;
    const int tid  = threadIdx.x;
    const int row  = row0 + tid;

    const float* qp = g_q + ((size_t)bh * SEQ + row) * HD;
    float qr[HD];
    #pragma unroll
    for (int d = 0; d < HD; d += 4) {
        float4 q4 = *(const float4*)(qp + d);
        qr[d + 0] = q4.x * scale; qr[d + 1] = q4.y * scale;
        qr[d + 2] = q4.z * scale; qr[d + 3] = q4.w * scale;
    }

    float o[HD];
    #pragma unroll
    for (int d = 0; d < HD; ++d) o[d] = 0.f;
    float m = -1e30f, l = 0.f;

    const float* kbase = g_k + (size_t)bh * SEQ * HD;
    const float* vbase = g_v + (size_t)bh * SEQ * HD;
    const int ntile = (row0 + 128) / 64;

    for (int tIdx = 0; tIdx < ntile; ++tIdx) {
        const int c0 = tIdx * 64;
        __syncthreads();
        #pragma unroll
        for (int u = 0; u < 8; ++u) {
            const int idx = (u * 128 + tid) * 4;
            *(float4*)&Ks[idx] = *(const float4*)(kbase + (size_t)c0 * HD + idx);
            *(float4*)&Vs[idx] = *(const float4*)(vbase + (size_t)c0 * HD + idx);
        }
        __syncthreads();

        #pragma unroll 1
        for (int jc = 0; jc < 64; jc += 8) {
            float s[8];
            #pragma unroll
            for (int jj = 0; jj < 8; ++jj) {
                const float* kr = &Ks[(jc + jj) * HD];
                float a = 0.f;
                #pragma unroll
                for (int d = 0; d < HD; ++d) a += qr[d] * kr[d];
                const int col = c0 + jc + jj;
                s[jj] = (col <= row) ? a : -1e30f;
            }
            float cmax = s[0];
            #pragma unroll
            for (int jj = 1; jj < 8; ++jj) cmax = fmaxf(cmax, s[jj]);
            if (cmax > m) {
                const float alpha = __expf(m - cmax);
                m = cmax;
                l *= alpha;
                #pragma unroll
                for (int d = 0; d < HD; ++d) o[d] *= alpha;
            }
            #pragma unroll
            for (int jj = 0; jj < 8; ++jj) {
                const float p = __expf(s[jj] - m);
                l += p;
                const float* vr = &Vs[(jc + jj) * HD];
                #pragma unroll
                for (int d = 0; d < HD; ++d) o[d] += p * vr[d];
            }
        }
    }

    const float inv = 1.f / l;
    const int bb = bh >> 4;
    const int hh = bh & (NH - 1);
    const size_t base = ((size_t)bb * SEQ + row) * DM + hh * HD;
    #pragma unroll
    for (int d = 0; d < HD; d += 2) {
        const float v0 = o[d] * inv, v1 = o[d + 1] * inv;
        __nv_bfloat16 h0, h1, l0, l1;
        split_bf16(v0, h0, l0);
        split_bf16(v1, h1, l1);
        __nv_bfloat162 ph(h0, h1), pl(l0, l1);
        *(uint32_t*)(g_ahi + base + d) = *(uint32_t*)&ph;
        *(uint32_t*)(g_alo + base + d) = *(uint32_t*)&pl;
    }
}

// ---------------- launch ----------------------------------------------------
extern "C" void kernel_launch(void* const* d_in, const int* in_sizes, int n_in,
                              void* d_out, int out_size)
{
    const float* x      = (const float*)d_in[0];
    const float* w_qkv  = (const float*)d_in[1];
    const float* b_qkv  = (const float*)d_in[2];
    const float* w_proj = (const float*)d_in[3];
    const float* b_proj = (const float*)d_in[4];
    float* out = (float*)d_out;

    cudaFuncSetAttribute(hmma_gemm<1>, cudaFuncAttributeMaxDynamicSharedMemorySize, TS_TOTAL);
    cudaFuncSetAttribute(hmma_gemm<2>, cudaFuncAttributeMaxDynamicSharedMemorySize, TS_TOTAL);

    __nv_bfloat16 *p_xhi, *p_xlo, *p_wqh, *p_wql, *p_wph, *p_wpl, *p_ahi, *p_alo;
    cudaGetSymbolAddress((void**)&p_xhi, g_xhi);
    cudaGetSymbolAddress((void**)&p_xlo, g_xlo);
    cudaGetSymbolAddress((void**)&p_wqh, g_wqh);
    cudaGetSymbolAddress((void**)&p_wql, g_wql);
    cudaGetSymbolAddress((void**)&p_wph, g_wph);
    cudaGetSymbolAddress((void**)&p_wpl, g_wpl);
    cudaGetSymbolAddress((void**)&p_ahi, g_ahi);
    cudaGetSymbolAddress((void**)&p_alo, g_alo);

    // 1) split x to bf16 hi/lo
    conv_split_kernel<<<(MTOT * DM) / (256 * 4), 256>>>(x, p_xhi, p_xlo);
    // 2) transpose+split weights
    transpose_conv_kernel<<<dim3(3 * DM / 32, DM / 32), dim3(32, 8)>>>(w_qkv, p_wqh, p_wql, DM, 3 * DM);
    transpose_conv_kernel<<<dim3(DM / 32, DM / 32), dim3(32, 8)>>>(w_proj, p_wph, p_wpl, DM, DM);
    // 3) QKV projection (HMMA tensor cores) -> g_q/g_k/g_v
    hmma_gemm<1><<<dim3(3 * DM / 128, MTOT / 128), 256, TS_TOTAL>>>(
        p_xhi, p_xlo, p_wqh, p_wql, b_qkv, nullptr, 3 * DM, DM);
    // 4) causal flash attention -> g_ahi/g_alo
    flash_kernel<<<dim3(SEQ / 128, BATCH * NH), 128>>>(0.125f);
    // 5) output projection (HMMA tensor cores) -> out
    hmma_gemm<2><<<dim3(DM / 128, MTOT / 128), 256, TS_TOTAL>>>(
        p_ahi, p_alo, p_wph, p_wpl, b_proj, out, DM, DM);
}

// round 13
// speedup vs baseline: 5.1078x; 2.0977x over previous
#include <cuda_runtime.h>
#include <cuda_bf16.h>
#include <cuda_fp16.h>
#include <cstdint>
#include <math.h>

#define BATCH 2
#define SEQ   2048
#define DM    1024
#define NH    16
#define HD    64
#define MTOT  (BATCH * SEQ)          // 4096
#define QS    0.18033688011112042f   // 0.125 * log2(e)

// ---------------- static scratch (no allocation APIs) ----------------------
static __device__ __nv_bfloat16 g_qh[(size_t)BATCH * NH * SEQ * HD];  // scaled q hi/lo
static __device__ __nv_bfloat16 g_ql[(size_t)BATCH * NH * SEQ * HD];
static __device__ __nv_bfloat16 g_kh[(size_t)BATCH * NH * SEQ * HD];
static __device__ __nv_bfloat16 g_kl[(size_t)BATCH * NH * SEQ * HD];
static __device__ __half        g_vh[(size_t)BATCH * NH * SEQ * HD];
static __device__ __half        g_vl[(size_t)BATCH * NH * SEQ * HD];

static __device__ __nv_bfloat16 g_xhi[(size_t)MTOT * DM];     // x split  [M,K]
static __device__ __nv_bfloat16 g_xlo[(size_t)MTOT * DM];
static __device__ __nv_bfloat16 g_wqh[(size_t)3 * DM * DM];   // w_qkv^T  [N,K]
static __device__ __nv_bfloat16 g_wql[(size_t)3 * DM * DM];
static __device__ __nv_bfloat16 g_wph[(size_t)DM * DM];       // w_proj^T [N,K]
static __device__ __nv_bfloat16 g_wpl[(size_t)DM * DM];
static __device__ __nv_bfloat16 g_ahi[(size_t)MTOT * DM];     // attn out  [M,K]
static __device__ __nv_bfloat16 g_alo[(size_t)MTOT * DM];

// ---------------- helpers ---------------------------------------------------
__device__ __forceinline__ uint32_t smem_to_u32(const void* p) {
    uint32_t a;
    asm("{ .reg .u64 t; cvta.to.shared.u64 t, %1; cvt.u32.u64 %0, t; }" : "=r"(a) : "l"(p));
    return a;
}
__device__ __forceinline__ void cp_async16(uint32_t s, const void* g) {
    asm volatile("cp.async.cg.shared.global [%0], [%1], 16;" :: "r"(s), "l"(g) : "memory");
}
__device__ __forceinline__ void ldsm4(uint32_t* r, uint32_t a) {
    asm volatile("ldmatrix.sync.aligned.m8n8.x4.shared.b16 {%0,%1,%2,%3}, [%4];"
                 : "=r"(r[0]), "=r"(r[1]), "=r"(r[2]), "=r"(r[3]) : "r"(a));
}
__device__ __forceinline__ void ldsm2(uint32_t* r, uint32_t a) {
    asm volatile("ldmatrix.sync.aligned.m8n8.x2.shared.b16 {%0,%1}, [%2];"
                 : "=r"(r[0]), "=r"(r[1]) : "r"(a));
}
__device__ __forceinline__ void ldsm2t(uint32_t* r, uint32_t a) {
    asm volatile("ldmatrix.sync.aligned.m8n8.x2.trans.shared.b16 {%0,%1}, [%2];"
                 : "=r"(r[0]), "=r"(r[1]) : "r"(a));
}
__device__ __forceinline__ void mma_bf16(float* c, const uint32_t* a, const uint32_t* b) {
    asm volatile(
        "mma.sync.aligned.m16n8k16.row.col.f32.bf16.bf16.f32 "
        "{%0,%1,%2,%3}, {%4,%5,%6,%7}, {%8,%9}, {%0,%1,%2,%3};"
        : "+f"(c[0]), "+f"(c[1]), "+f"(c[2]), "+f"(c[3])
        : "r"(a[0]), "r"(a[1]), "r"(a[2]), "r"(a[3]), "r"(b[0]), "r"(b[1]));
}
__device__ __forceinline__ void mma_f16(float* c, const uint32_t* a, const uint32_t* b) {
    asm volatile(
        "mma.sync.aligned.m16n8k16.row.col.f32.f16.f16.f32 "
        "{%0,%1,%2,%3}, {%4,%5,%6,%7}, {%8,%9}, {%0,%1,%2,%3};"
        : "+f"(c[0]), "+f"(c[1]), "+f"(c[2]), "+f"(c[3])
        : "r"(a[0]), "r"(a[1]), "r"(a[2]), "r"(a[3]), "r"(b[0]), "r"(b[1]));
}
// p = ex2(s) for a pair, packed f16x2 (s0 -> low, s1 -> high)
__device__ __forceinline__ uint32_t ex2_f16x2(float s0, float s1) {
    uint32_t h, p;
    asm("cvt.rn.f16x2.f32 %0, %1, %2;" : "=r"(h) : "f"(s1), "f"(s0));
    asm("ex2.approx.f16x2 %0, %1;" : "=r"(p) : "r"(h));
    return p;
}
__device__ __forceinline__ void split_bf16(float v, __nv_bfloat16& h, __nv_bfloat16& l) {
    h = __float2bfloat16(v);
    l = __float2bfloat16(v - __bfloat162float(h));
}
__device__ __forceinline__ void split_half(float v, __half& h, __half& l) {
    h = __float2half(v);
    l = __float2half(v - __half2float(h));
}

// QKV epilogue scatter: q (scaled) / k -> bf16 hi/lo, v -> fp16 hi/lo, [B*H, T, 64]
__device__ __forceinline__ void store_qkv(int col, int r, float2 v) {
    const int which = col >> 10;
    const int hh = (col & (DM - 1)) >> 6;
    const int d0 = col & (HD - 1);
    const int bb = r >> 11, tt = r & (SEQ - 1);
    const size_t idx = ((size_t)(bb * NH + hh) * SEQ + tt) * HD + d0;
    if (which == 2) {
        __half h0, h1, l0, l1;
        split_half(v.x, h0, l0);
        split_half(v.y, h1, l1);
        __half2 ph(h0, h1), pl(l0, l1);
        *(uint32_t*)(g_vh + idx) = *(uint32_t*)&ph;
        *(uint32_t*)(g_vl + idx) = *(uint32_t*)&pl;
    } else {
        float sx = v.x, sy = v.y;
        if (which == 0) { sx *= QS; sy *= QS; }
        __nv_bfloat16 h0, h1, l0, l1;
        split_bf16(sx, h0, l0);
        split_bf16(sy, h1, l1);
        __nv_bfloat162 ph(h0, h1), pl(l0, l1);
        __nv_bfloat16* dh = which ? g_kh : g_qh;
        __nv_bfloat16* dl = which ? g_kl : g_ql;
        *(uint32_t*)(dh + idx) = *(uint32_t*)&ph;
        *(uint32_t*)(dl + idx) = *(uint32_t*)&pl;
    }
}

// ---------------- prep kernels ---------------------------------------------
__global__ __launch_bounds__(256)
void conv_split_kernel(const float* __restrict__ src,
                       __nv_bfloat16* __restrict__ dhi, __nv_bfloat16* __restrict__ dlo)
{
    const size_t i = ((size_t)blockIdx.x * 256 + threadIdx.x) * 4;
    float4 v = *(const float4*)(src + i);
    __nv_bfloat16 h0, h1, h2, h3, l0, l1, l2, l3;
    split_bf16(v.x, h0, l0); split_bf16(v.y, h1, l1);
    split_bf16(v.z, h2, l2); split_bf16(v.w, h3, l3);
    __nv_bfloat162 ph0(h0, h1), ph1(h2, h3), pl0(l0, l1), pl1(l2, l3);
    uint2 uh = make_uint2(*(uint32_t*)&ph0, *(uint32_t*)&ph1);
    uint2 ul = make_uint2(*(uint32_t*)&pl0, *(uint32_t*)&pl1);
    *(uint2*)(dhi + i) = uh;
    *(uint2*)(dlo + i) = ul;
}

__global__ __launch_bounds__(256)
void transpose_conv_kernel(const float* __restrict__ src,
                           __nv_bfloat16* __restrict__ dhi, __nv_bfloat16* __restrict__ dlo,
                           int K, int N)
{
    __shared__ float t[32][33];
    const int n0 = blockIdx.x * 32, k0 = blockIdx.y * 32;
    #pragma unroll
    for (int i = 0; i < 4; ++i)
        t[threadIdx.y + i * 8][threadIdx.x] =
            src[(size_t)(k0 + threadIdx.y + i * 8) * N + n0 + threadIdx.x];
    __syncthreads();
    #pragma unroll
    for (int i = 0; i < 4; ++i) {
        const int n = n0 + threadIdx.y + i * 8;
        const int k = k0 + threadIdx.x;
        __nv_bfloat16 h, l;
        split_bf16(t[threadIdx.x][threadIdx.y + i * 8], h, l);
        dhi[(size_t)n * K + k] = h;
        dlo[(size_t)n * K + k] = l;
    }
}

// ---------------- HMMA split-bf16 GEMM (from R12, MODE1 epilogue changed) --
#define TS_ROW   80u
#define TS_MAT   (128u * TS_ROW)
#define TS_STAGE (4u * TS_MAT)
#define TS_TOTAL (2u * TS_STAGE)

template<int MODE>   // 1 = QKV scatter epilogue, 2 = plain C epilogue
__global__ __launch_bounds__(256)
void hmma_gemm(const __nv_bfloat16* __restrict__ Ahi, const __nv_bfloat16* __restrict__ Alo,
               const __nv_bfloat16* __restrict__ Bhi, const __nv_bfloat16* __restrict__ Blo,
               const float* __restrict__ bias, float* __restrict__ Cout, int Ncols, int K)
{
    extern __shared__ char smem[];
    const uint32_t sbase = smem_to_u32(smem);
    const int tid = threadIdx.x, lane = tid & 31, wid = tid >> 5;
    const int warp_m = wid & 1, warp_n = wid >> 1;
    const int bm0 = blockIdx.y * 128, bn0 = blockIdx.x * 128;

    auto issue_stage = [&](int c, int stage) {
        const int k0 = c << 5;
        #pragma unroll
        for (int i = 0; i < 8; ++i) {
            const int lin  = i * 256 + tid;
            const int mat  = lin >> 9;
            const int rem  = lin & 511;
            const int row  = rem >> 2;
            const int unit = rem & 3;
            const __nv_bfloat16* src = (mat == 0) ? Ahi : (mat == 1) ? Alo
                                     : (mat == 2) ? Bhi : Blo;
            const int grow = ((mat < 2) ? bm0 : bn0) + row;
            const void* g = src + (size_t)grow * K + k0 + unit * 8;
            const uint32_t s = sbase + stage * TS_STAGE + mat * TS_MAT
                             + row * TS_ROW + unit * 16;
            cp_async16(s, g);
        }
        asm volatile("cp.async.commit_group;" ::: "memory");
    };

    float acc[4][4][4];
    #pragma unroll
    for (int mt = 0; mt < 4; ++mt)
        #pragma unroll
        for (int nt = 0; nt < 4; ++nt)
            #pragma unroll
            for (int e = 0; e < 4; ++e) acc[mt][nt][e] = 0.f;

    const int nchunk = K >> 5;
    issue_stage(0, 0);

    for (int c = 0; c < nchunk; ++c) {
        if (c + 1 < nchunk) {
            issue_stage(c + 1, (c + 1) & 1);
            asm volatile("cp.async.wait_group 1;" ::: "memory");
        } else {
            asm volatile("cp.async.wait_group 0;" ::: "memory");
        }
        __syncthreads();

        const uint32_t st = sbase + (uint32_t)(c & 1) * TS_STAGE;
        #pragma unroll
        for (int ks = 0; ks < 2; ++ks) {
            uint32_t ahi[4][4], alo[4][4], bhi[4][2], blo[4][2];
            const int arow = warp_m * 64 + (lane & 15);
            const uint32_t acol = (uint32_t)(ks * 32 + (lane >> 4) * 16);
            #pragma unroll
            for (int mt = 0; mt < 4; ++mt) {
                const uint32_t a = st + (uint32_t)(arow + mt * 16) * TS_ROW + acol;
                ldsm4(ahi[mt], a);
                ldsm4(alo[mt], a + TS_MAT);
            }
            const int brow = warp_n * 32 + ((lane & 15) & 7);
            const uint32_t bcol = (uint32_t)(ks * 32 + (((lane & 15) >> 3)) * 16);
            #pragma unroll
            for (int nt = 0; nt < 4; ++nt) {
                const uint32_t b = st + 2u * TS_MAT + (uint32_t)(brow + nt * 8) * TS_ROW + bcol;
                ldsm2(bhi[nt], b);
                ldsm2(blo[nt], b + TS_MAT);
            }
            #pragma unroll
            for (int mt = 0; mt < 4; ++mt)
                #pragma unroll
                for (int nt = 0; nt < 4; ++nt) {
                    mma_bf16(acc[mt][nt], ahi[mt], bhi[nt]);
                    mma_bf16(acc[mt][nt], ahi[mt], blo[nt]);
                    mma_bf16(acc[mt][nt], alo[mt], bhi[nt]);
                }
        }
        __syncthreads();
    }

    const int gid = lane >> 2, tig = lane & 3;
    #pragma unroll
    for (int mt = 0; mt < 4; ++mt) {
        const int r1 = bm0 + warp_m * 64 + mt * 16 + gid;
        const int r2 = r1 + 8;
        #pragma unroll
        for (int nt = 0; nt < 4; ++nt) {
            const int col = bn0 + warp_n * 32 + nt * 8 + tig * 2;
            const float b0 = bias[col], b1 = bias[col + 1];
            float2 v1 = make_float2(acc[mt][nt][0] + b0, acc[mt][nt][1] + b1);
            float2 v2 = make_float2(acc[mt][nt][2] + b0, acc[mt][nt][3] + b1);
            if (MODE == 1) {
                store_qkv(col, r1, v1);
                store_qkv(col, r2, v2);
            } else {
                *(float2*)(Cout + (size_t)r1 * Ncols + col) = v1;
                *(float2*)(Cout + (size_t)r2 * Ncols + col) = v2;
            }
        }
    }
}

// ---------------- HMMA flash attention (causal) ----------------------------
// 256 thr / 8 warps, warp owns 16 Q rows. Br=128, Kc=64. Base-2 softmax
// (scale folded into q). S = 3-term bf16 split; P = f16 via ex2.approx.f16x2;
// PV = f16 MMA with V hi/lo; l via MMA against ones.
#define FPB   144u               // smem row pitch bytes (64 elems data + pad)
#define SQH   0u
#define SQL   18432u
#define SKH   36864u
#define SKL   46080u
#define SVH   55296u
#define SVL   64512u
#define FS_TOTAL 73728u

__global__ __launch_bounds__(256)
void flash_hmma()
{
    extern __shared__ char smem[];
    const uint32_t sbase = smem_to_u32(smem);
    const int tid = threadIdx.x, lane = tid & 31, wid = tid >> 5;
    const int bh = blockIdx.y;
    const int rt = (gridDim.x - 1) - blockIdx.x;         // heavy tiles first
    const int row0 = rt * 128;
    const int r0w = row0 + wid * 16;
    const size_t bh_base = (size_t)bh * SEQ * HD;

    // ---- Q tile load (once): 2 mats x 128 rows x 8x16B = 2048 units
    #pragma unroll
    for (int i = 0; i < 8; ++i) {
        const int lin = i * 256 + tid;
        const int mat = lin >> 10;
        const int row = (lin >> 3) & 127;
        const int unit = lin & 7;
        const __nv_bfloat16* src = mat ? g_ql : g_qh;
        cp_async16(sbase + SQH + mat * 18432u + row * FPB + unit * 16u,
                   src + bh_base + (size_t)(row0 + row) * HD + unit * 8);
    }
    asm volatile("cp.async.commit_group;" ::: "memory");

    uint32_t qh[4][4], ql[4][4];
    float m2a = -1e30f, m2b = -1e30f, la = 0.f, lb = 0.f;
    float o[8][4];
    #pragma unroll
    for (int n = 0; n < 8; ++n)
        #pragma unroll
        for (int e = 0; e < 4; ++e) o[n][e] = 0.f;

    const int gid = lane >> 2, tig = lane & 3;
    const int rowa = r0w + gid;
    const int ntile = (row0 + 128) >> 6;

    for (int t = 0; t < ntile; ++t) {
        const int j0 = t << 6;
        __syncthreads();                   // previous K/V consumed
        // K/V tile: 4 mats x 64 rows x 8x16B = 2048 units
        #pragma unroll
        for (int i = 0; i < 8; ++i) {
            const int lin = i * 256 + tid;
            const int mat = lin >> 9;
            const int rem = lin & 511;
            const int row = rem >> 3;
            const int unit = rem & 7;
            const void* src;
            if (mat == 0)      src = g_kh + bh_base + (size_t)(j0 + row) * HD + unit * 8;
            else if (mat == 1) src = g_kl + bh_base + (size_t)(j0 + row) * HD + unit * 8;
            else if (mat == 2) src = g_vh + bh_base + (size_t)(j0 + row) * HD + unit * 8;
            else               src = g_vl + bh_base + (size_t)(j0 + row) * HD + unit * 8;
            cp_async16(sbase + SKH + mat * 9216u + row * FPB + unit * 16u, src);
        }
        asm volatile("cp.async.commit_group;" ::: "memory");
        asm volatile("cp.async.wait_group 0;" ::: "memory");
        __syncthreads();

        if (t == 0) {
            const uint32_t qa = sbase + SQH + (uint32_t)(wid * 16 + (lane & 15)) * FPB
                              + (uint32_t)(lane >> 4) * 16u;
            #pragma unroll
            for (int ks = 0; ks < 4; ++ks) {
                ldsm4(qh[ks], qa + ks * 32u);
                ldsm4(ql[ks], qa + 18432u + ks * 32u);
            }
        }

        if (j0 <= r0w + 15) {
            // ---- S = Q K^T (3-term split), fp32 frags
            float s[8][4];
            #pragma unroll
            for (int nt = 0; nt < 8; ++nt) {
                #pragma unroll
                for (int e = 0; e < 4; ++e) s[nt][e] = 0.f;
                const uint32_t kb = sbase + SKH
                    + (uint32_t)(nt * 8 + ((lane & 15) & 7)) * FPB
                    + (uint32_t)(((lane & 15) >> 3)) * 16u;
                #pragma unroll
                for (int ks = 0; ks < 4; ++ks) {
                    uint32_t kh[2], kl[2];
                    ldsm2(kh, kb + ks * 32u);
                    ldsm2(kl, kb + 9216u + ks * 32u);
                    mma_bf16(s[nt], qh[ks], kh);
                    mma_bf16(s[nt], qh[ks], kl);
                    mma_bf16(s[nt], ql[ks], kh);
                }
            }
            // ---- causal mask
            if (j0 + 63 > r0w) {
                #pragma unroll
                for (int nt = 0; nt < 8; ++nt) {
                    const int c0 = j0 + nt * 8 + tig * 2;
                    if (c0     > rowa)     s[nt][0] = -1e30f;
                    if (c0 + 1 > rowa)     s[nt][1] = -1e30f;
                    if (c0     > rowa + 8) s[nt][2] = -1e30f;
                    if (c0 + 1 > rowa + 8) s[nt][3] = -1e30f;
                }
            }
            // ---- online softmax (base-2)
            float mx0 = -1e30f, mx1 = -1e30f;
            #pragma unroll
            for (int nt = 0; nt < 8; ++nt) {
                mx0 = fmaxf(mx0, fmaxf(s[nt][0], s[nt][1]));
                mx1 = fmaxf(mx1, fmaxf(s[nt][2], s[nt][3]));
            }
            mx0 = fmaxf(mx0, __shfl_xor_sync(0xFFFFFFFFu, mx0, 1));
            mx0 = fmaxf(mx0, __shfl_xor_sync(0xFFFFFFFFu, mx0, 2));
            mx1 = fmaxf(mx1, __shfl_xor_sync(0xFFFFFFFFu, mx1, 1));
            mx1 = fmaxf(mx1, __shfl_xor_sync(0xFFFFFFFFu, mx1, 2));
            const float mna = fmaxf(m2a, mx0), mnb = fmaxf(m2b, mx1);
            const float alpa = exp2f(m2a - mna), alpb = exp2f(m2b - mnb);
            m2a = mna; m2b = mnb;
            la *= alpa; lb *= alpb;
            #pragma unroll
            for (int n = 0; n < 8; ++n) {
                o[n][0] *= alpa; o[n][1] *= alpa;
                o[n][2] *= alpb; o[n][3] *= alpb;
            }
            uint32_t p01[8], p23[8];
            #pragma unroll
            for (int nt = 0; nt < 8; ++nt) {
                p01[nt] = ex2_f16x2(s[nt][0] - mna, s[nt][1] - mna);
                p23[nt] = ex2_f16x2(s[nt][2] - mnb, s[nt][3] - mnb);
            }
            // ---- l += row-sum(P) via MMA with ones
            {
                float lacc[4] = {0.f, 0.f, 0.f, 0.f};
                const uint32_t ones = 0x3C003C00u;
                uint32_t ob[2] = {ones, ones};
                #pragma unroll
                for (int ks = 0; ks < 4; ++ks) {
                    uint32_t ap[4] = {p01[2 * ks], p23[2 * ks],
                                      p01[2 * ks + 1], p23[2 * ks + 1]};
                    mma_f16(lacc, ap, ob);
                }
                la += lacc[0]; lb += lacc[2];
            }
            // ---- O += P V (V hi + lo)
            #pragma unroll
            for (int ks = 0; ks < 4; ++ks) {
                uint32_t ap[4] = {p01[2 * ks], p23[2 * ks],
                                  p01[2 * ks + 1], p23[2 * ks + 1]};
                const uint32_t va = sbase + SVH
                    + (uint32_t)(ks * 16 + (lane & 15)) * FPB;
                #pragma unroll
                for (int nd = 0; nd < 8; ++nd) {
                    uint32_t vh[2], vl[2];
                    ldsm2t(vh, va + nd * 16u);
                    ldsm2t(vl, va + 9216u + nd * 16u);
                    mma_f16(o[nd], ap, vh);
                    mma_f16(o[nd], ap, vl);
                }
            }
        }
    }

    // ---- epilogue: normalize, split to bf16 hi/lo for proj GEMM
    const float inva = 1.f / la, invb = 1.f / lb;
    const int bb = bh >> 4, hh = bh & (NH - 1);
    const int r1 = rowa, r2 = rowa + 8;
    #pragma unroll
    for (int nd = 0; nd < 8; ++nd) {
        const int col = hh * HD + nd * 8 + tig * 2;
        const size_t i1 = ((size_t)(bb * SEQ + r1)) * DM + col;
        const size_t i2 = ((size_t)(bb * SEQ + r2)) * DM + col;
        __nv_bfloat16 h0, h1, l0, l1;
        split_bf16(o[nd][0] * inva, h0, l0);
        split_bf16(o[nd][1] * inva, h1, l1);
        __nv_bfloat162 ph(h0, h1), pl(l0, l1);
        *(uint32_t*)(g_ahi + i1) = *(uint32_t*)&ph;
        *(uint32_t*)(g_alo + i1) = *(uint32_t*)&pl;
        split_bf16(o[nd][2] * invb, h0, l0);
        split_bf16(o[nd][3] * invb, h1, l1);
        __nv_bfloat162 qh2(h0, h1), ql2(l0, l1);
        *(uint32_t*)(g_ahi + i2) = *(uint32_t*)&qh2;
        *(uint32_t*)(g_alo + i2) = *(uint32_t*)&ql2;
    }
}

// ---------------- launch ----------------------------------------------------
extern "C" void kernel_launch(void* const* d_in, const int* in_sizes, int n_in,
                              void* d_out, int out_size)
{
    const float* x      = (const float*)d_in[0];
    const float* w_qkv  = (const float*)d_in[1];
    const float* b_qkv  = (const float*)d_in[2];
    const float* w_proj = (const float*)d_in[3];
    const float* b_proj = (const float*)d_in[4];
    float* out = (float*)d_out;

    cudaFuncSetAttribute(hmma_gemm<1>, cudaFuncAttributeMaxDynamicSharedMemorySize, TS_TOTAL);
    cudaFuncSetAttribute(hmma_gemm<2>, cudaFuncAttributeMaxDynamicSharedMemorySize, TS_TOTAL);
    cudaFuncSetAttribute(flash_hmma,   cudaFuncAttributeMaxDynamicSharedMemorySize, FS_TOTAL);

    __nv_bfloat16 *p_xhi, *p_xlo, *p_wqh, *p_wql, *p_wph, *p_wpl, *p_ahi, *p_alo;
    cudaGetSymbolAddress((void**)&p_xhi, g_xhi);
    cudaGetSymbolAddress((void**)&p_xlo, g_xlo);
    cudaGetSymbolAddress((void**)&p_wqh, g_wqh);
    cudaGetSymbolAddress((void**)&p_wql, g_wql);
    cudaGetSymbolAddress((void**)&p_wph, g_wph);
    cudaGetSymbolAddress((void**)&p_wpl, g_wpl);
    cudaGetSymbolAddress((void**)&p_ahi, g_ahi);
    cudaGetSymbolAddress((void**)&p_alo, g_alo);

    // 1) split x to bf16 hi/lo
    conv_split_kernel<<<(MTOT * DM) / (256 * 4), 256>>>(x, p_xhi, p_xlo);
    // 2) transpose+split weights
    transpose_conv_kernel<<<dim3(3 * DM / 32, DM / 32), dim3(32, 8)>>>(w_qkv, p_wqh, p_wql, DM, 3 * DM);
    transpose_conv_kernel<<<dim3(DM / 32, DM / 32), dim3(32, 8)>>>(w_proj, p_wph, p_wpl, DM, DM);
    // 3) QKV projection (HMMA) -> q/k bf16 hi/lo (q pre-scaled), v fp16 hi/lo
    hmma_gemm<1><<<dim3(3 * DM / 128, MTOT / 128), 256, TS_TOTAL>>>(
        p_xhi, p_xlo, p_wqh, p_wql, b_qkv, nullptr, 3 * DM, DM);
    // 4) causal flash attention (HMMA) -> g_ahi/g_alo
    flash_hmma<<<dim3(SEQ / 128, BATCH * NH), 256, FS_TOTAL>>>();
    // 5) output projection (HMMA) -> out
    hmma_gemm<2><<<dim3(DM / 128, MTOT / 128), 256, TS_TOTAL>>>(
        p_ahi, p_alo, p_wph, p_wpl, b_proj, out, DM, DM);
}

// round 15
// speedup vs baseline: 5.2835x; 1.0344x over previous
#include <cuda_runtime.h>
#include <cuda_bf16.h>
#include <cuda_fp16.h>
#include <cstdint>
#include <math.h>

#define BATCH 2
#define SEQ   2048
#define DM    1024
#define NH    16
#define HD    64
#define MTOT  (BATCH * SEQ)          // 4096
#define QS    0.18033688011112042f   // 0.125 * log2(e)

// ---------------- static scratch (no allocation APIs) ----------------------
static __device__ __nv_bfloat16 g_qh[(size_t)BATCH * NH * SEQ * HD];  // scaled q hi/lo
static __device__ __nv_bfloat16 g_ql[(size_t)BATCH * NH * SEQ * HD];
static __device__ __nv_bfloat16 g_kh[(size_t)BATCH * NH * SEQ * HD];
static __device__ __nv_bfloat16 g_kl[(size_t)BATCH * NH * SEQ * HD];
static __device__ __half        g_vh[(size_t)BATCH * NH * SEQ * HD];
static __device__ __half        g_vl[(size_t)BATCH * NH * SEQ * HD];

static __device__ __nv_bfloat16 g_xhi[(size_t)MTOT * DM];     // x split  [M,K]
static __device__ __nv_bfloat16 g_xlo[(size_t)MTOT * DM];
static __device__ __nv_bfloat16 g_wqh[(size_t)3 * DM * DM];   // w_qkv^T  [N,K]
static __device__ __nv_bfloat16 g_wql[(size_t)3 * DM * DM];
static __device__ __nv_bfloat16 g_wph[(size_t)DM * DM];       // w_proj^T [N,K]
static __device__ __nv_bfloat16 g_wpl[(size_t)DM * DM];
static __device__ __nv_bfloat16 g_ahi[(size_t)MTOT * DM];     // attn out  [M,K]
static __device__ __nv_bfloat16 g_alo[(size_t)MTOT * DM];

// ---------------- helpers ---------------------------------------------------
__device__ __forceinline__ uint32_t smem_to_u32(const void* p) {
    uint32_t a;
    asm("{ .reg .u64 t; cvta.to.shared.u64 t, %1; cvt.u32.u64 %0, t; }" : "=r"(a) : "l"(p));
    return a;
}
__device__ __forceinline__ void cp_async16(uint32_t s, const void* g) {
    asm volatile("cp.async.cg.shared.global [%0], [%1], 16;" :: "r"(s), "l"(g) : "memory");
}
__device__ __forceinline__ void ldsm4(uint32_t* r, uint32_t a) {
    asm volatile("ldmatrix.sync.aligned.m8n8.x4.shared.b16 {%0,%1,%2,%3}, [%4];"
                 : "=r"(r[0]), "=r"(r[1]), "=r"(r[2]), "=r"(r[3]) : "r"(a));
}
__device__ __forceinline__ void ldsm2(uint32_t* r, uint32_t a) {
    asm volatile("ldmatrix.sync.aligned.m8n8.x2.shared.b16 {%0,%1}, [%2];"
                 : "=r"(r[0]), "=r"(r[1]) : "r"(a));
}
__device__ __forceinline__ void ldsm2t(uint32_t* r, uint32_t a) {
    asm volatile("ldmatrix.sync.aligned.m8n8.x2.trans.shared.b16 {%0,%1}, [%2];"
                 : "=r"(r[0]), "=r"(r[1]) : "r"(a));
}
__device__ __forceinline__ void mma_bf16(float* c, const uint32_t* a, const uint32_t* b) {
    asm volatile(
        "mma.sync.aligned.m16n8k16.row.col.f32.bf16.bf16.f32 "
        "{%0,%1,%2,%3}, {%4,%5,%6,%7}, {%8,%9}, {%0,%1,%2,%3};"
        : "+f"(c[0]), "+f"(c[1]), "+f"(c[2]), "+f"(c[3])
        : "r"(a[0]), "r"(a[1]), "r"(a[2]), "r"(a[3]), "r"(b[0]), "r"(b[1]));
}
__device__ __forceinline__ void mma_f16(float* c, const uint32_t* a, const uint32_t* b) {
    asm volatile(
        "mma.sync.aligned.m16n8k16.row.col.f32.f16.f16.f32 "
        "{%0,%1,%2,%3}, {%4,%5,%6,%7}, {%8,%9}, {%0,%1,%2,%3};"
        : "+f"(c[0]), "+f"(c[1]), "+f"(c[2]), "+f"(c[3])
        : "r"(a[0]), "r"(a[1]), "r"(a[2]), "r"(a[3]), "r"(b[0]), "r"(b[1]));
}
// p = ex2(s) for a pair, packed f16x2 (s0 -> low, s1 -> high)
__device__ __forceinline__ uint32_t ex2_f16x2(float s0, float s1) {
    uint32_t h, p;
    asm("cvt.rn.f16x2.f32 %0, %1, %2;" : "=r"(h) : "f"(s1), "f"(s0));
    asm("ex2.approx.f16x2 %0, %1;" : "=r"(p) : "r"(h));
    return p;
}
__device__ __forceinline__ void split_bf16(float v, __nv_bfloat16& h, __nv_bfloat16& l) {
    h = __float2bfloat16(v);
    l = __float2bfloat16(v - __bfloat162float(h));
}
__device__ __forceinline__ void split_half(float v, __half& h, __half& l) {
    h = __float2half(v);
    l = __float2half(v - __half2float(h));
}

// QKV epilogue scatter: q (scaled) / k -> bf16 hi/lo, v -> fp16 hi/lo, [B*H, T, 64]
__device__ __forceinline__ void store_qkv(int col, int r, float2 v) {
    const int which = col >> 10;
    const int hh = (col & (DM - 1)) >> 6;
    const int d0 = col & (HD - 1);
    const int bb = r >> 11, tt = r & (SEQ - 1);
    const size_t idx = ((size_t)(bb * NH + hh) * SEQ + tt) * HD + d0;
    if (which == 2) {
        __half h0, h1, l0, l1;
        split_half(v.x, h0, l0);
        split_half(v.y, h1, l1);
        __half2 ph(h0, h1), pl(l0, l1);
        *(uint32_t*)(g_vh + idx) = *(uint32_t*)&ph;
        *(uint32_t*)(g_vl + idx) = *(uint32_t*)&pl;
    } else {
        float sx = v.x, sy = v.y;
        if (which == 0) { sx *= QS; sy *= QS; }
        __nv_bfloat16 h0, h1, l0, l1;
        split_bf16(sx, h0, l0);
        split_bf16(sy, h1, l1);
        __nv_bfloat162 ph(h0, h1), pl(l0, l1);
        __nv_bfloat16* dh = which ? g_kh : g_qh;
        __nv_bfloat16* dl = which ? g_kl : g_ql;
        *(uint32_t*)(dh + idx) = *(uint32_t*)&ph;
        *(uint32_t*)(dl + idx) = *(uint32_t*)&pl;
    }
}

// ---------------- prep kernels ---------------------------------------------
__global__ __launch_bounds__(256)
void conv_split_kernel(const float* __restrict__ src,
                       __nv_bfloat16* __restrict__ dhi, __nv_bfloat16* __restrict__ dlo)
{
    const size_t i = ((size_t)blockIdx.x * 256 + threadIdx.x) * 4;
    float4 v = *(const float4*)(src + i);
    __nv_bfloat16 h0, h1, h2, h3, l0, l1, l2, l3;
    split_bf16(v.x, h0, l0); split_bf16(v.y, h1, l1);
    split_bf16(v.z, h2, l2); split_bf16(v.w, h3, l3);
    __nv_bfloat162 ph0(h0, h1), ph1(h2, h3), pl0(l0, l1), pl1(l2, l3);
    uint2 uh = make_uint2(*(uint32_t*)&ph0, *(uint32_t*)&ph1);
    uint2 ul = make_uint2(*(uint32_t*)&pl0, *(uint32_t*)&pl1);
    *(uint2*)(dhi + i) = uh;
    *(uint2*)(dlo + i) = ul;
}

__global__ __launch_bounds__(256)
void transpose_conv_kernel(const float* __restrict__ src,
                           __nv_bfloat16* __restrict__ dhi, __nv_bfloat16* __restrict__ dlo,
                           int K, int N)
{
    __shared__ float t[32][33];
    const int n0 = blockIdx.x * 32, k0 = blockIdx.y * 32;
    #pragma unroll
    for (int i = 0; i < 4; ++i)
        t[threadIdx.y + i * 8][threadIdx.x] =
            src[(size_t)(k0 + threadIdx.y + i * 8) * N + n0 + threadIdx.x];
    __syncthreads();
    #pragma unroll
    for (int i = 0; i < 4; ++i) {
        const int n = n0 + threadIdx.y + i * 8;
        const int k = k0 + threadIdx.x;
        __nv_bfloat16 h, l;
        split_bf16(t[threadIdx.x][threadIdx.y + i * 8], h, l);
        dhi[(size_t)n * K + k] = h;
        dlo[(size_t)n * K + k] = l;
    }
}

// ---------------- HMMA split-bf16 GEMM -------------------------------------
// Term-major MMA passes: all hi*hi (16 independent accs), then hi*lo, then
// lo*hi -- RAW distance on each accumulator is 16 MMAs in program order.
#define TS_ROW   80u
#define TS_MAT   (128u * TS_ROW)
#define TS_STAGE (4u * TS_MAT)
#define TS_TOTAL (2u * TS_STAGE)

template<int MODE>   // 1 = QKV scatter epilogue, 2 = plain C epilogue
__global__ __launch_bounds__(256)
void hmma_gemm(const __nv_bfloat16* __restrict__ Ahi, const __nv_bfloat16* __restrict__ Alo,
               const __nv_bfloat16* __restrict__ Bhi, const __nv_bfloat16* __restrict__ Blo,
               const float* __restrict__ bias, float* __restrict__ Cout, int Ncols, int K)
{
    extern __shared__ char smem[];
    const uint32_t sbase = smem_to_u32(smem);
    const int tid = threadIdx.x, lane = tid & 31, wid = tid >> 5;
    const int warp_m = wid & 1, warp_n = wid >> 1;
    const int bm0 = blockIdx.y * 128, bn0 = blockIdx.x * 128;

    auto issue_stage = [&](int c, int stage) {
        const int k0 = c << 5;
        #pragma unroll
        for (int i = 0; i < 8; ++i) {
            const int lin  = i * 256 + tid;
            const int mat  = lin >> 9;
            const int rem  = lin & 511;
            const int row  = rem >> 2;
            const int unit = rem & 3;
            const __nv_bfloat16* src = (mat == 0) ? Ahi : (mat == 1) ? Alo
                                     : (mat == 2) ? Bhi : Blo;
            const int grow = ((mat < 2) ? bm0 : bn0) + row;
            const void* g = src + (size_t)grow * K + k0 + unit * 8;
            const uint32_t s = sbase + stage * TS_STAGE + mat * TS_MAT
                             + row * TS_ROW + unit * 16;
            cp_async16(s, g);
        }
        asm volatile("cp.async.commit_group;" ::: "memory");
    };

    float acc[4][4][4];
    #pragma unroll
    for (int mt = 0; mt < 4; ++mt)
        #pragma unroll
        for (int nt = 0; nt < 4; ++nt)
            #pragma unroll
            for (int e = 0; e < 4; ++e) acc[mt][nt][e] = 0.f;

    const int nchunk = K >> 5;
    issue_stage(0, 0);

    for (int c = 0; c < nchunk; ++c) {
        if (c + 1 < nchunk) {
            issue_stage(c + 1, (c + 1) & 1);
            asm volatile("cp.async.wait_group 1;" ::: "memory");
        } else {
            asm volatile("cp.async.wait_group 0;" ::: "memory");
        }
        __syncthreads();

        const uint32_t st = sbase + (uint32_t)(c & 1) * TS_STAGE;
        #pragma unroll
        for (int ks = 0; ks < 2; ++ks) {
            uint32_t ahi[4][4], alo[4][4], bhi[4][2], blo[4][2];
            const int arow = warp_m * 64 + (lane & 15);
            const uint32_t acol = (uint32_t)(ks * 32 + (lane >> 4) * 16);
            #pragma unroll
            for (int mt = 0; mt < 4; ++mt) {
                const uint32_t a = st + (uint32_t)(arow + mt * 16) * TS_ROW + acol;
                ldsm4(ahi[mt], a);
                ldsm4(alo[mt], a + TS_MAT);
            }
            const int brow = warp_n * 32 + ((lane & 15) & 7);
            const uint32_t bcol = (uint32_t)(ks * 32 + (((lane & 15) >> 3)) * 16);
            #pragma unroll
            for (int nt = 0; nt < 4; ++nt) {
                const uint32_t b = st + 2u * TS_MAT + (uint32_t)(brow + nt * 8) * TS_ROW + bcol;
                ldsm2(bhi[nt], b);
                ldsm2(blo[nt], b + TS_MAT);
            }
            // term-major: 3 passes of 16 independent MMAs
            #pragma unroll
            for (int mt = 0; mt < 4; ++mt)
                #pragma unroll
                for (int nt = 0; nt < 4; ++nt)
                    mma_bf16(acc[mt][nt], ahi[mt], bhi[nt]);
            #pragma unroll
            for (int mt = 0; mt < 4; ++mt)
                #pragma unroll
                for (int nt = 0; nt < 4; ++nt)
                    mma_bf16(acc[mt][nt], ahi[mt], blo[nt]);
            #pragma unroll
            for (int mt = 0; mt < 4; ++mt)
                #pragma unroll
                for (int nt = 0; nt < 4; ++nt)
                    mma_bf16(acc[mt][nt], alo[mt], bhi[nt]);
        }
        __syncthreads();
    }

    const int gid = lane >> 2, tig = lane & 3;
    #pragma unroll
    for (int mt = 0; mt < 4; ++mt) {
        const int r1 = bm0 + warp_m * 64 + mt * 16 + gid;
        const int r2 = r1 + 8;
        #pragma unroll
        for (int nt = 0; nt < 4; ++nt) {
            const int col = bn0 + warp_n * 32 + nt * 8 + tig * 2;
            const float b0 = bias[col], b1 = bias[col + 1];
            float2 v1 = make_float2(acc[mt][nt][0] + b0, acc[mt][nt][1] + b1);
            float2 v2 = make_float2(acc[mt][nt][2] + b0, acc[mt][nt][3] + b1);
            if (MODE == 1) {
                store_qkv(col, r1, v1);
                store_qkv(col, r2, v2);
            } else {
                *(float2*)(Cout + (size_t)r1 * Ncols + col) = v1;
                *(float2*)(Cout + (size_t)r2 * Ncols + col) = v2;
            }
        }
    }
}

// ---------------- HMMA flash attention (causal) ----------------------------
// 256 thr / 8 warps, warp owns 16 Q rows. Br=128, Kc=64, base-2 softmax.
// K/V tiles are 2-stage cp.async double-buffered: tile t+1 loads while tile t
// computes. Smem: Q hi/lo (36KB) + 2 x KV stage (36KB each) = 108KB.
#define FPB   144u               // smem row pitch bytes (64 elems data + pad)
#define SQH   0u
#define SQL   18432u
#define SKV   36864u             // KV stage base; stage stride 36864
#define KVST  36864u
#define OKL   9216u              // in-stage: KH +0, KL +9216, VH +18432, VL +27648
#define OVH   18432u
#define FS_TOTAL 110592u

__global__ __launch_bounds__(256)
void flash_hmma()
{
    extern __shared__ char smem[];
    const uint32_t sbase = smem_to_u32(smem);
    const int tid = threadIdx.x, lane = tid & 31, wid = tid >> 5;
    const int bh = blockIdx.y;
    const int rt = (gridDim.x - 1) - blockIdx.x;         // heavy tiles first
    const int row0 = rt * 128;
    const int r0w = row0 + wid * 16;
    const size_t bh_base = (size_t)bh * SEQ * HD;

    auto issue_kv = [&](int t, int stage) {
        const int j0 = t << 6;
        #pragma unroll
        for (int i = 0; i < 8; ++i) {
            const int lin = i * 256 + tid;
            const int mat = lin >> 9;
            const int rem = lin & 511;
            const int row = rem >> 3;
            const int unit = rem & 7;
            const void* src;
            if (mat == 0)      src = g_kh + bh_base + (size_t)(j0 + row) * HD + unit * 8;
            else if (mat == 1) src = g_kl + bh_base + (size_t)(j0 + row) * HD + unit * 8;
            else if (mat == 2) src = g_vh + bh_base + (size_t)(j0 + row) * HD + unit * 8;
            else               src = g_vl + bh_base + (size_t)(j0 + row) * HD + unit * 8;
            cp_async16(sbase + SKV + (uint32_t)stage * KVST + mat * 9216u
                       + row * FPB + unit * 16u, src);
        }
        asm volatile("cp.async.commit_group;" ::: "memory");
    };

    // ---- Q tile load (once): 2 mats x 128 rows x 8x16B = 2048 units
    #pragma unroll
    for (int i = 0; i < 8; ++i) {
        const int lin = i * 256 + tid;
        const int mat = lin >> 10;
        const int row = (lin >> 3) & 127;
        const int unit = lin & 7;
        const __nv_bfloat16* src = mat ? g_ql : g_qh;
        cp_async16(sbase + SQH + mat * 18432u + row * FPB + unit * 16u,
                   src + bh_base + (size_t)(row0 + row) * HD + unit * 8);
    }
    asm volatile("cp.async.commit_group;" ::: "memory");

    uint32_t qh[4][4], ql[4][4];
    float m2a = -1e30f, m2b = -1e30f, la = 0.f, lb = 0.f;
    float o[8][4];
    #pragma unroll
    for (int n = 0; n < 8; ++n)
        #pragma unroll
        for (int e = 0; e < 4; ++e) o[n][e] = 0.f;

    const int gid = lane >> 2, tig = lane & 3;
    const int rowa = r0w + gid;
    const int ntile = (row0 + 128) >> 6;

    issue_kv(0, 0);

    for (int t = 0; t < ntile; ++t) {
        const int j0 = t << 6;
        if (t + 1 < ntile) {
            issue_kv(t + 1, (t + 1) & 1);
            asm volatile("cp.async.wait_group 1;" ::: "memory");
        } else {
            asm volatile("cp.async.wait_group 0;" ::: "memory");
        }
        __syncthreads();

        if (t == 0) {
            const uint32_t qa = sbase + SQH + (uint32_t)(wid * 16 + (lane & 15)) * FPB
                              + (uint32_t)(lane >> 4) * 16u;
            #pragma unroll
            for (int ks = 0; ks < 4; ++ks) {
                ldsm4(qh[ks], qa + ks * 32u);
                ldsm4(ql[ks], qa + 18432u + ks * 32u);
            }
        }

        if (j0 <= r0w + 15) {
            const uint32_t stg = sbase + SKV + (uint32_t)(t & 1) * KVST;
            // ---- S = Q K^T (3-term split), term-major for ILP
            float s[8][4];
            uint32_t kh[8][2], kl[8][2];
            #pragma unroll
            for (int nt = 0; nt < 8; ++nt) {
                #pragma unroll
                for (int e = 0; e < 4; ++e) s[nt][e] = 0.f;
            }
            #pragma unroll
            for (int ks = 0; ks < 4; ++ks) {
                #pragma unroll
                for (int nt = 0; nt < 8; ++nt) {
                    const uint32_t kb = stg
                        + (uint32_t)(nt * 8 + ((lane & 15) & 7)) * FPB
                        + (uint32_t)(((lane & 15) >> 3)) * 16u + ks * 32u;
                    ldsm2(kh[nt], kb);
                    ldsm2(kl[nt], kb + OKL);
                }
                #pragma unroll
                for (int nt = 0; nt < 8; ++nt) mma_bf16(s[nt], qh[ks], kh[nt]);
                #pragma unroll
                for (int nt = 0; nt < 8; ++nt) mma_bf16(s[nt], qh[ks], kl[nt]);
                #pragma unroll
                for (int nt = 0; nt < 8; ++nt) mma_bf16(s[nt], ql[ks], kh[nt]);
            }
            // ---- causal mask
            if (j0 + 63 > r0w) {
                #pragma unroll
                for (int nt = 0; nt < 8; ++nt) {
                    const int c0 = j0 + nt * 8 + tig * 2;
                    if (c0     > rowa)     s[nt][0] = -1e30f;
                    if (c0 + 1 > rowa)     s[nt][1] = -1e30f;
                    if (c0     > rowa + 8) s[nt][2] = -1e30f;
                    if (c0 + 1 > rowa + 8) s[nt][3] = -1e30f;
                }
            }
            // ---- online softmax (base-2)
            float mx0 = -1e30f, mx1 = -1e30f;
            #pragma unroll
            for (int nt = 0; nt < 8; ++nt) {
                mx0 = fmaxf(mx0, fmaxf(s[nt][0], s[nt][1]));
                mx1 = fmaxf(mx1, fmaxf(s[nt][2], s[nt][3]));
            }
            mx0 = fmaxf(mx0, __shfl_xor_sync(0xFFFFFFFFu, mx0, 1));
            mx0 = fmaxf(mx0, __shfl_xor_sync(0xFFFFFFFFu, mx0, 2));
            mx1 = fmaxf(mx1, __shfl_xor_sync(0xFFFFFFFFu, mx1, 1));
            mx1 = fmaxf(mx1, __shfl_xor_sync(0xFFFFFFFFu, mx1, 2));
            const float mna = fmaxf(m2a, mx0), mnb = fmaxf(m2b, mx1);
            const float alpa = exp2f(m2a - mna), alpb = exp2f(m2b - mnb);
            m2a = mna; m2b = mnb;
            la *= alpa; lb *= alpb;
            #pragma unroll
            for (int n = 0; n < 8; ++n) {
                o[n][0] *= alpa; o[n][1] *= alpa;
                o[n][2] *= alpb; o[n][3] *= alpb;
            }
            uint32_t p01[8], p23[8];
            #pragma unroll
            for (int nt = 0; nt < 8; ++nt) {
                p01[nt] = ex2_f16x2(s[nt][0] - mna, s[nt][1] - mna);
                p23[nt] = ex2_f16x2(s[nt][2] - mnb, s[nt][3] - mnb);
            }
            // ---- l += row-sum(P) via MMA with ones
            {
                float lacc[4] = {0.f, 0.f, 0.f, 0.f};
                const uint32_t ones = 0x3C003C00u;
                uint32_t ob[2] = {ones, ones};
                #pragma unroll
                for (int ks = 0; ks < 4; ++ks) {
                    uint32_t ap[4] = {p01[2 * ks], p23[2 * ks],
                                      p01[2 * ks + 1], p23[2 * ks + 1]};
                    mma_f16(lacc, ap, ob);
                }
                la += lacc[0]; lb += lacc[2];
            }
            // ---- O += P V (V hi + lo)
            #pragma unroll
            for (int ks = 0; ks < 4; ++ks) {
                uint32_t ap[4] = {p01[2 * ks], p23[2 * ks],
                                  p01[2 * ks + 1], p23[2 * ks + 1]};
                const uint32_t va = stg + OVH
                    + (uint32_t)(ks * 16 + (lane & 15)) * FPB;
                #pragma unroll
                for (int nd = 0; nd < 8; ++nd) {
                    uint32_t vh[2], vl[2];
                    ldsm2t(vh, va + nd * 16u);
                    ldsm2t(vl, va + OKL + nd * 16u);
                    mma_f16(o[nd], ap, vh);
                    mma_f16(o[nd], ap, vl);
                }
            }
        }
        __syncthreads();   // stage consumed -> safe for issue at t+1
    }

    // ---- epilogue: normalize, split to bf16 hi/lo for proj GEMM
    const float inva = 1.f / la, invb = 1.f / lb;
    const int bb = bh >> 4, hh = bh & (NH - 1);
    const int r1 = rowa, r2 = rowa + 8;
    #pragma unroll
    for (int nd = 0; nd < 8; ++nd) {
        const int col = hh * HD + nd * 8 + tig * 2;
        const size_t i1 = ((size_t)(bb * SEQ + r1)) * DM + col;
        const size_t i2 = ((size_t)(bb * SEQ + r2)) * DM + col;
        __nv_bfloat16 h0, h1, l0, l1;
        split_bf16(o[nd][0] * inva, h0, l0);
        split_bf16(o[nd][1] * inva, h1, l1);
        __nv_bfloat162 ph(h0, h1), pl(l0, l1);
        *(uint32_t*)(g_ahi + i1) = *(uint32_t*)&ph;
        *(uint32_t*)(g_alo + i1) = *(uint32_t*)&pl;
        split_bf16(o[nd][2] * invb, h0, l0);
        split_bf16(o[nd][3] * invb, h1, l1);
        __nv_bfloat162 qh2(h0, h1), ql2(l0, l1);
        *(uint32_t*)(g_ahi + i2) = *(uint32_t*)&qh2;
        *(uint32_t*)(g_alo + i2) = *(uint32_t*)&ql2;
    }
}

// ---------------- launch ----------------------------------------------------
extern "C" void kernel_launch(void* const* d_in, const int* in_sizes, int n_in,
                              void* d_out, int out_size)
{
    const float* x      = (const float*)d_in[0];
    const float* w_qkv  = (const float*)d_in[1];
    const float* b_qkv  = (const float*)d_in[2];
    const float* w_proj = (const float*)d_in[3];
    const float* b_proj = (const float*)d_in[4];
    float* out = (float*)d_out;

    cudaFuncSetAttribute(hmma_gemm<1>, cudaFuncAttributeMaxDynamicSharedMemorySize, TS_TOTAL);
    cudaFuncSetAttribute(hmma_gemm<2>, cudaFuncAttributeMaxDynamicSharedMemorySize, TS_TOTAL);
    cudaFuncSetAttribute(flash_hmma,   cudaFuncAttributeMaxDynamicSharedMemorySize, FS_TOTAL);

    __nv_bfloat16 *p_xhi, *p_xlo, *p_wqh, *p_wql, *p_wph, *p_wpl, *p_ahi, *p_alo;
    cudaGetSymbolAddress((void**)&p_xhi, g_xhi);
    cudaGetSymbolAddress((void**)&p_xlo, g_xlo);
    cudaGetSymbolAddress((void**)&p_wqh, g_wqh);
    cudaGetSymbolAddress((void**)&p_wql, g_wql);
    cudaGetSymbolAddress((void**)&p_wph, g_wph);
    cudaGetSymbolAddress((void**)&p_wpl, g_wpl);
    cudaGetSymbolAddress((void**)&p_ahi, g_ahi);
    cudaGetSymbolAddress((void**)&p_alo, g_alo);

    // 1) split x to bf16 hi/lo
    conv_split_kernel<<<(MTOT * DM) / (256 * 4), 256>>>(x, p_xhi, p_xlo);
    // 2) transpose+split weights
    transpose_conv_kernel<<<dim3(3 * DM / 32, DM / 32), dim3(32, 8)>>>(w_qkv, p_wqh, p_wql, DM, 3 * DM);
    transpose_conv_kernel<<<dim3(DM / 32, DM / 32), dim3(32, 8)>>>(w_proj, p_wph, p_wpl, DM, DM);
    // 3) QKV projection (HMMA) -> q/k bf16 hi/lo (q pre-scaled), v fp16 hi/lo
    hmma_gemm<1><<<dim3(3 * DM / 128, MTOT / 128), 256, TS_TOTAL>>>(
        p_xhi, p_xlo, p_wqh, p_wql, b_qkv, nullptr, 3 * DM, DM);
    // 4) causal flash attention (HMMA) -> g_ahi/g_alo
    flash_hmma<<<dim3(SEQ / 128, BATCH * NH), 256, FS_TOTAL>>>();
    // 5) output projection (HMMA) -> out
    hmma_gemm<2><<<dim3(DM / 128, MTOT / 128), 256, TS_TOTAL>>>(
        p_ahi, p_alo, p_wph, p_wpl, b_proj, out, DM, DM);
}

// round 17
// speedup vs baseline: 7.7446x; 1.4658x over previous
#include <cuda_runtime.h>
#include <cuda_bf16.h>
#include <cuda_fp16.h>
#include <cstdint>
#include <math.h>

#define BATCH 2
#define SEQ   2048
#define DM    1024
#define NH    16
#define HD    64
#define MTOT  (BATCH * SEQ)          // 4096
#define QS    0.18033688011112042f   // 0.125 * log2(e)

// ---------------- static scratch (no allocation APIs) ----------------------
static __device__ __nv_bfloat16 g_qh[(size_t)BATCH * NH * SEQ * HD];  // scaled q hi/lo
static __device__ __nv_bfloat16 g_ql[(size_t)BATCH * NH * SEQ * HD];
static __device__ __nv_bfloat16 g_kh[(size_t)BATCH * NH * SEQ * HD];
static __device__ __nv_bfloat16 g_kl[(size_t)BATCH * NH * SEQ * HD];
static __device__ __half        g_vh[(size_t)BATCH * NH * SEQ * HD];
static __device__ __half        g_vl[(size_t)BATCH * NH * SEQ * HD];

static __device__ __half g_xf[(size_t)MTOT * DM];      // x f16        [M,K]
static __device__ __half g_wq[(size_t)3 * DM * DM];    // w_qkv^T f16  [N,K]
static __device__ __half g_wp[(size_t)DM * DM];        // w_proj^T f16 [N,K]
static __device__ __half g_af[(size_t)MTOT * DM];      // attn out f16 [M,K]

// ---------------- helpers ---------------------------------------------------
__device__ __forceinline__ uint32_t smem_to_u32(const void* p) {
    uint32_t a;
    asm("{ .reg .u64 t; cvta.to.shared.u64 t, %1; cvt.u32.u64 %0, t; }" : "=r"(a) : "l"(p));
    return a;
}
__device__ __forceinline__ void cp_async16(uint32_t s, const void* g) {
    asm volatile("cp.async.cg.shared.global [%0], [%1], 16;" :: "r"(s), "l"(g) : "memory");
}
__device__ __forceinline__ void ldsm4(uint32_t* r, uint32_t a) {
    asm volatile("ldmatrix.sync.aligned.m8n8.x4.shared.b16 {%0,%1,%2,%3}, [%4];"
                 : "=r"(r[0]), "=r"(r[1]), "=r"(r[2]), "=r"(r[3]) : "r"(a));
}
__device__ __forceinline__ void ldsm2(uint32_t* r, uint32_t a) {
    asm volatile("ldmatrix.sync.aligned.m8n8.x2.shared.b16 {%0,%1}, [%2];"
                 : "=r"(r[0]), "=r"(r[1]) : "r"(a));
}
__device__ __forceinline__ void ldsm2t(uint32_t* r, uint32_t a) {
    asm volatile("ldmatrix.sync.aligned.m8n8.x2.trans.shared.b16 {%0,%1}, [%2];"
                 : "=r"(r[0]), "=r"(r[1]) : "r"(a));
}
__device__ __forceinline__ void mma_bf16(float* c, const uint32_t* a, const uint32_t* b) {
    asm volatile(
        "mma.sync.aligned.m16n8k16.row.col.f32.bf16.bf16.f32 "
        "{%0,%1,%2,%3}, {%4,%5,%6,%7}, {%8,%9}, {%0,%1,%2,%3};"
        : "+f"(c[0]), "+f"(c[1]), "+f"(c[2]), "+f"(c[3])
        : "r"(a[0]), "r"(a[1]), "r"(a[2]), "r"(a[3]), "r"(b[0]), "r"(b[1]));
}
__device__ __forceinline__ void mma_f16(float* c, const uint32_t* a, const uint32_t* b) {
    asm volatile(
        "mma.sync.aligned.m16n8k16.row.col.f32.f16.f16.f32 "
        "{%0,%1,%2,%3}, {%4,%5,%6,%7}, {%8,%9}, {%0,%1,%2,%3};"
        : "+f"(c[0]), "+f"(c[1]), "+f"(c[2]), "+f"(c[3])
        : "r"(a[0]), "r"(a[1]), "r"(a[2]), "r"(a[3]), "r"(b[0]), "r"(b[1]));
}
// p = ex2(s) for a pair, packed f16x2 (s0 -> low, s1 -> high)
__device__ __forceinline__ uint32_t ex2_f16x2(float s0, float s1) {
    uint32_t h, p;
    asm("cvt.rn.f16x2.f32 %0, %1, %2;" : "=r"(h) : "f"(s1), "f"(s0));
    asm("ex2.approx.f16x2 %0, %1;" : "=r"(p) : "r"(h));
    return p;
}
__device__ __forceinline__ void split_bf16(float v, __nv_bfloat16& h, __nv_bfloat16& l) {
    h = __float2bfloat16(v);
    l = __float2bfloat16(v - __bfloat162float(h));
}
__device__ __forceinline__ void split_half(float v, __half& h, __half& l) {
    h = __float2half(v);
    l = __float2half(v - __half2float(h));
}

// QKV epilogue scatter: q (scaled) / k -> bf16 hi/lo, v -> fp16 hi/lo, [B*H, T, 64]
__device__ __forceinline__ void store_qkv(int col, int r, float2 v) {
    const int which = col >> 10;
    const int hh = (col & (DM - 1)) >> 6;
    const int d0 = col & (HD - 1);
    const int bb = r >> 11, tt = r & (SEQ - 1);
    const size_t idx = ((size_t)(bb * NH + hh) * SEQ + tt) * HD + d0;
    if (which == 2) {
        __half h0, h1, l0, l1;
        split_half(v.x, h0, l0);
        split_half(v.y, h1, l1);
        __half2 ph(h0, h1), pl(l0, l1);
        *(uint32_t*)(g_vh + idx) = *(uint32_t*)&ph;
        *(uint32_t*)(g_vl + idx) = *(uint32_t*)&pl;
    } else {
        float sx = v.x, sy = v.y;
        if (which == 0) { sx *= QS; sy *= QS; }
        __nv_bfloat16 h0, h1, l0, l1;
        split_bf16(sx, h0, l0);
        split_bf16(sy, h1, l1);
        __nv_bfloat162 ph(h0, h1), pl(l0, l1);
        __nv_bfloat16* dh = which ? g_kh : g_qh;
        __nv_bfloat16* dl = which ? g_kl : g_ql;
        *(uint32_t*)(dh + idx) = *(uint32_t*)&ph;
        *(uint32_t*)(dl + idx) = *(uint32_t*)&pl;
    }
}

// ---------------- prep kernels ---------------------------------------------
__global__ __launch_bounds__(256)
void conv_f16_kernel(const float* __restrict__ src, __half* __restrict__ dst)
{
    const size_t i = ((size_t)blockIdx.x * 256 + threadIdx.x) * 4;
    float4 v = *(const float4*)(src + i);
    __half2 p0(__float2half(v.x), __float2half(v.y));
    __half2 p1(__float2half(v.z), __float2half(v.w));
    uint2 u = make_uint2(*(uint32_t*)&p0, *(uint32_t*)&p1);
    *(uint2*)(dst + i) = u;
}

// Transpose: src fp32 [K,N] -> dst f16 [N,K]
__global__ __launch_bounds__(256)
void transpose_f16_kernel(const float* __restrict__ src, __half* __restrict__ dst,
                          int K, int N)
{
    __shared__ float t[32][33];
    const int n0 = blockIdx.x * 32, k0 = blockIdx.y * 32;
    #pragma unroll
    for (int i = 0; i < 4; ++i)
        t[threadIdx.y + i * 8][threadIdx.x] =
            src[(size_t)(k0 + threadIdx.y + i * 8) * N + n0 + threadIdx.x];
    __syncthreads();
    #pragma unroll
    for (int i = 0; i < 4; ++i) {
        const int n = n0 + threadIdx.y + i * 8;
        const int k = k0 + threadIdx.x;
        dst[(size_t)n * K + k] = __float2half(t[threadIdx.x][threadIdx.y + i * 8]);
    }
}

// ---------------- HMMA f16 GEMM (single precision term) --------------------
// C[128x128] = A[M,K] @ B^T, A/B K-major f16. 256 thr, warp tile 64x32.
// 3-stage cp.async pipeline; smem = 3 x 20KB = 60KB.
#define TS_ROW   80u
#define TS_MAT   (128u * TS_ROW)     // 10240
#define TS_STAGE (2u * TS_MAT)       // 20480
#define TS_TOTAL (3u * TS_STAGE)     // 61440

template<int MODE>   // 1 = QKV scatter epilogue, 2 = plain C epilogue
__global__ __launch_bounds__(256)
void hmma_gemm(const __half* __restrict__ A, const __half* __restrict__ B,
               const float* __restrict__ bias, float* __restrict__ Cout,
               int Ncols, int K)
{
    extern __shared__ char smem[];
    const uint32_t sbase = smem_to_u32(smem);
    const int tid = threadIdx.x, lane = tid & 31, wid = tid >> 5;
    const int warp_m = wid & 1, warp_n = wid >> 1;
    const int bm0 = blockIdx.y * 128, bn0 = blockIdx.x * 128;

    // 2 mats x 128 rows x 4 x 16B = 1024 cp.async (4 per thread)
    auto issue_stage = [&](int c, int stage) {
        const int k0 = c << 5;
        #pragma unroll
        for (int i = 0; i < 4; ++i) {
            const int lin  = i * 256 + tid;
            const int mat  = lin >> 9;
            const int rem  = lin & 511;
            const int row  = rem >> 2;
            const int unit = rem & 3;
            const __half* src = mat ? B : A;
            const int grow = (mat ? bn0 : bm0) + row;
            const void* g = src + (size_t)grow * K + k0 + unit * 8;
            const uint32_t s = sbase + (uint32_t)stage * TS_STAGE + mat * TS_MAT
                             + row * TS_ROW + unit * 16;
            cp_async16(s, g);
        }
        asm volatile("cp.async.commit_group;" ::: "memory");
    };

    float acc[4][4][4];
    #pragma unroll
    for (int mt = 0; mt < 4; ++mt)
        #pragma unroll
        for (int nt = 0; nt < 4; ++nt)
            #pragma unroll
            for (int e = 0; e < 4; ++e) acc[mt][nt][e] = 0.f;

    const int nchunk = K >> 5;
    issue_stage(0, 0);
    if (nchunk > 1) issue_stage(1, 1);

    int stage = 0;
    for (int c = 0; c < nchunk; ++c) {
        if (c + 2 < nchunk) {
            issue_stage(c + 2, (stage + 2) % 3);
            asm volatile("cp.async.wait_group 2;" ::: "memory");
        } else if (c + 1 < nchunk) {
            asm volatile("cp.async.wait_group 1;" ::: "memory");
        } else {
            asm volatile("cp.async.wait_group 0;" ::: "memory");
        }
        __syncthreads();

        const uint32_t st = sbase + (uint32_t)stage * TS_STAGE;
        #pragma unroll
        for (int ks = 0; ks < 2; ++ks) {
            uint32_t af[4][4], bf[4][2];
            const int arow = warp_m * 64 + (lane & 15);
            const uint32_t acol = (uint32_t)(ks * 32 + (lane >> 4) * 16);
            #pragma unroll
            for (int mt = 0; mt < 4; ++mt)
                ldsm4(af[mt], st + (uint32_t)(arow + mt * 16) * TS_ROW + acol);
            const int brow = warp_n * 32 + ((lane & 15) & 7);
            const uint32_t bcol = (uint32_t)(ks * 32 + (((lane & 15) >> 3)) * 16);
            #pragma unroll
            for (int nt = 0; nt < 4; ++nt)
                ldsm2(bf[nt], st + TS_MAT + (uint32_t)(brow + nt * 8) * TS_ROW + bcol);
            #pragma unroll
            for (int mt = 0; mt < 4; ++mt)
                #pragma unroll
                for (int nt = 0; nt < 4; ++nt)
                    mma_f16(acc[mt][nt], af[mt], bf[nt]);
        }
        __syncthreads();
        stage = (stage + 1) % 3;
    }

    const int gid = lane >> 2, tig = lane & 3;
    #pragma unroll
    for (int mt = 0; mt < 4; ++mt) {
        const int r1 = bm0 + warp_m * 64 + mt * 16 + gid;
        const int r2 = r1 + 8;
        #pragma unroll
        for (int nt = 0; nt < 4; ++nt) {
            const int col = bn0 + warp_n * 32 + nt * 8 + tig * 2;
            const float b0 = bias[col], b1 = bias[col + 1];
            float2 v1 = make_float2(acc[mt][nt][0] + b0, acc[mt][nt][1] + b1);
            float2 v2 = make_float2(acc[mt][nt][2] + b0, acc[mt][nt][3] + b1);
            if (MODE == 1) {
                store_qkv(col, r1, v1);
                store_qkv(col, r2, v2);
            } else {
                *(float2*)(Cout + (size_t)r1 * Ncols + col) = v1;
                *(float2*)(Cout + (size_t)r2 * Ncols + col) = v2;
            }
        }
    }
}

// ---------------- HMMA flash attention (causal) ----------------------------
// 256 thr / 8 warps, warp owns 16 Q rows. Br=128, Kc=64, base-2 softmax.
// K/V tiles 2-stage cp.async double-buffered. Smem 108KB.
#define FPB   144u               // smem row pitch bytes (64 elems data + pad)
#define SQH   0u
#define SQL   18432u
#define SKV   36864u             // KV stage base; stage stride 36864
#define KVST  36864u
#define OKL   9216u              // in-stage: KH +0, KL +9216, VH +18432, VL +27648
#define OVH   18432u
#define FS_TOTAL 110592u

__global__ __launch_bounds__(256)
void flash_hmma()
{
    extern __shared__ char smem[];
    const uint32_t sbase = smem_to_u32(smem);
    const int tid = threadIdx.x, lane = tid & 31, wid = tid >> 5;
    const int bh = blockIdx.y;
    const int rt = (gridDim.x - 1) - blockIdx.x;         // heavy tiles first
    const int row0 = rt * 128;
    const int r0w = row0 + wid * 16;
    const size_t bh_base = (size_t)bh * SEQ * HD;

    auto issue_kv = [&](int t, int stage) {
        const int j0 = t << 6;
        #pragma unroll
        for (int i = 0; i < 8; ++i) {
            const int lin = i * 256 + tid;
            const int mat = lin >> 9;
            const int rem = lin & 511;
            const int row = rem >> 3;
            const int unit = rem & 7;
            const void* src;
            if (mat == 0)      src = g_kh + bh_base + (size_t)(j0 + row) * HD + unit * 8;
            else if (mat == 1) src = g_kl + bh_base + (size_t)(j0 + row) * HD + unit * 8;
            else if (mat == 2) src = g_vh + bh_base + (size_t)(j0 + row) * HD + unit * 8;
            else               src = g_vl + bh_base + (size_t)(j0 + row) * HD + unit * 8;
            cp_async16(sbase + SKV + (uint32_t)stage * KVST + mat * 9216u
                       + row * FPB + unit * 16u, src);
        }
        asm volatile("cp.async.commit_group;" ::: "memory");
    };

    // ---- Q tile load (once): 2 mats x 128 rows x 8x16B = 2048 units
    #pragma unroll
    for (int i = 0; i < 8; ++i) {
        const int lin = i * 256 + tid;
        const int mat = lin >> 10;
        const int row = (lin >> 3) & 127;
        const int unit = lin & 7;
        const __nv_bfloat16* src = mat ? g_ql : g_qh;
        cp_async16(sbase + SQH + mat * 18432u + row * FPB + unit * 16u,
                   src + bh_base + (size_t)(row0 + row) * HD + unit * 8);
    }
    asm volatile("cp.async.commit_group;" ::: "memory");

    uint32_t qh[4][4], ql[4][4];
    float m2a = -1e30f, m2b = -1e30f, la = 0.f, lb = 0.f;
    float o[8][4];
    #pragma unroll
    for (int n = 0; n < 8; ++n)
        #pragma unroll
        for (int e = 0; e < 4; ++e) o[n][e] = 0.f;

    const int gid = lane >> 2, tig = lane & 3;
    const int rowa = r0w + gid;
    const int ntile = (row0 + 128) >> 6;

    issue_kv(0, 0);

    for (int t = 0; t < ntile; ++t) {
        const int j0 = t << 6;
        if (t + 1 < ntile) {
            issue_kv(t + 1, (t + 1) & 1);
            asm volatile("cp.async.wait_group 1;" ::: "memory");
        } else {
            asm volatile("cp.async.wait_group 0;" ::: "memory");
        }
        __syncthreads();

        if (t == 0) {
            const uint32_t qa = sbase + SQH + (uint32_t)(wid * 16 + (lane & 15)) * FPB
                              + (uint32_t)(lane >> 4) * 16u;
            #pragma unroll
            for (int ks = 0; ks < 4; ++ks) {
                ldsm4(qh[ks], qa + ks * 32u);
                ldsm4(ql[ks], qa + 18432u + ks * 32u);
            }
        }

        if (j0 <= r0w + 15) {
            const uint32_t stg = sbase + SKV + (uint32_t)(t & 1) * KVST;
            // ---- S = Q K^T (3-term split), term-major for ILP
            float s[8][4];
            uint32_t kh[8][2], kl[8][2];
            #pragma unroll
            for (int nt = 0; nt < 8; ++nt) {
                #pragma unroll
                for (int e = 0; e < 4; ++e) s[nt][e] = 0.f;
            }
            #pragma unroll
            for (int ks = 0; ks < 4; ++ks) {
                #pragma unroll
                for (int nt = 0; nt < 8; ++nt) {
                    const uint32_t kb = stg
                        + (uint32_t)(nt * 8 + ((lane & 15) & 7)) * FPB
                        + (uint32_t)(((lane & 15) >> 3)) * 16u + ks * 32u;
                    ldsm2(kh[nt], kb);
                    ldsm2(kl[nt], kb + OKL);
                }
                #pragma unroll
                for (int nt = 0; nt < 8; ++nt) mma_bf16(s[nt], qh[ks], kh[nt]);
                #pragma unroll
                for (int nt = 0; nt < 8; ++nt) mma_bf16(s[nt], qh[ks], kl[nt]);
                #pragma unroll
                for (int nt = 0; nt < 8; ++nt) mma_bf16(s[nt], ql[ks], kh[nt]);
            }
            // ---- causal mask
            if (j0 + 63 > r0w) {
                #pragma unroll
                for (int nt = 0; nt < 8; ++nt) {
                    const int c0 = j0 + nt * 8 + tig * 2;
                    if (c0     > rowa)     s[nt][0] = -1e30f;
                    if (c0 + 1 > rowa)     s[nt][1] = -1e30f;
                    if (c0     > rowa + 8) s[nt][2] = -1e30f;
                    if (c0 + 1 > rowa + 8) s[nt][3] = -1e30f;
                }
            }
            // ---- online softmax (base-2)
            float mx0 = -1e30f, mx1 = -1e30f;
            #pragma unroll
            for (int nt = 0; nt < 8; ++nt) {
                mx0 = fmaxf(mx0, fmaxf(s[nt][0], s[nt][1]));
                mx1 = fmaxf(mx1, fmaxf(s[nt][2], s[nt][3]));
            }
            mx0 = fmaxf(mx0, __shfl_xor_sync(0xFFFFFFFFu, mx0, 1));
            mx0 = fmaxf(mx0, __shfl_xor_sync(0xFFFFFFFFu, mx0, 2));
            mx1 = fmaxf(mx1, __shfl_xor_sync(0xFFFFFFFFu, mx1, 1));
            mx1 = fmaxf(mx1, __shfl_xor_sync(0xFFFFFFFFu, mx1, 2));
            const float mna = fmaxf(m2a, mx0), mnb = fmaxf(m2b, mx1);
            const float alpa = exp2f(m2a - mna), alpb = exp2f(m2b - mnb);
            m2a = mna; m2b = mnb;
            la *= alpa; lb *= alpb;
            #pragma unroll
            for (int n = 0; n < 8; ++n) {
                o[n][0] *= alpa; o[n][1] *= alpa;
                o[n][2] *= alpb; o[n][3] *= alpb;
            }
            uint32_t p01[8], p23[8];
            #pragma unroll
            for (int nt = 0; nt < 8; ++nt) {
                p01[nt] = ex2_f16x2(s[nt][0] - mna, s[nt][1] - mna);
                p23[nt] = ex2_f16x2(s[nt][2] - mnb, s[nt][3] - mnb);
            }
            // ---- l += row-sum(P) via MMA with ones
            {
                float lacc[4] = {0.f, 0.f, 0.f, 0.f};
                const uint32_t ones = 0x3C003C00u;
                uint32_t ob[2] = {ones, ones};
                #pragma unroll
                for (int ks = 0; ks < 4; ++ks) {
                    uint32_t ap[4] = {p01[2 * ks], p23[2 * ks],
                                      p01[2 * ks + 1], p23[2 * ks + 1]};
                    mma_f16(lacc, ap, ob);
                }
                la += lacc[0]; lb += lacc[2];
            }
            // ---- O += P V (V hi + lo)
            #pragma unroll
            for (int ks = 0; ks < 4; ++ks) {
                uint32_t ap[4] = {p01[2 * ks], p23[2 * ks],
                                  p01[2 * ks + 1], p23[2 * ks + 1]};
                const uint32_t va = stg + OVH
                    + (uint32_t)(ks * 16 + (lane & 15)) * FPB;
                #pragma unroll
                for (int nd = 0; nd < 8; ++nd) {
                    uint32_t vh[2], vl[2];
                    ldsm2t(vh, va + nd * 16u);
                    ldsm2t(vl, va + OKL + nd * 16u);
                    mma_f16(o[nd], ap, vh);
                    mma_f16(o[nd], ap, vl);
                }
            }
        }
        __syncthreads();   // stage consumed -> safe for issue at t+1
    }

    // ---- epilogue: normalize, store f16 for proj GEMM
    const float inva = 1.f / la, invb = 1.f / lb;
    const int bb = bh >> 4, hh = bh & (NH - 1);
    const int r1 = rowa, r2 = rowa + 8;
    #pragma unroll
    for (int nd = 0; nd < 8; ++nd) {
        const int col = hh * HD + nd * 8 + tig * 2;
        const size_t i1 = ((size_t)(bb * SEQ + r1)) * DM + col;
        const size_t i2 = ((size_t)(bb * SEQ + r2)) * DM + col;
        __half2 h1(__float2half(o[nd][0] * inva), __float2half(o[nd][1] * inva));
        __half2 h2(__float2half(o[nd][2] * invb), __float2half(o[nd][3] * invb));
        *(uint32_t*)(g_af + i1) = *(uint32_t*)&h1;
        *(uint32_t*)(g_af + i2) = *(uint32_t*)&h2;
    }
}

// ---------------- launch ----------------------------------------------------
extern "C" void kernel_launch(void* const* d_in, const int* in_sizes, int n_in,
                              void* d_out, int out_size)
{
    const float* x      = (const float*)d_in[0];
    const float* w_qkv  = (const float*)d_in[1];
    const float* b_qkv  = (const float*)d_in[2];
    const float* w_proj = (const float*)d_in[3];
    const float* b_proj = (const float*)d_in[4];
    float* out = (float*)d_out;

    cudaFuncSetAttribute(hmma_gemm<1>, cudaFuncAttributeMaxDynamicSharedMemorySize, TS_TOTAL);
    cudaFuncSetAttribute(hmma_gemm<2>, cudaFuncAttributeMaxDynamicSharedMemorySize, TS_TOTAL);
    cudaFuncSetAttribute(flash_hmma,   cudaFuncAttributeMaxDynamicSharedMemorySize, FS_TOTAL);

    __half *p_xf, *p_wq, *p_wp, *p_af;
    cudaGetSymbolAddress((void**)&p_xf, g_xf);
    cudaGetSymbolAddress((void**)&p_wq, g_wq);
    cudaGetSymbolAddress((void**)&p_wp, g_wp);
    cudaGetSymbolAddress((void**)&p_af, g_af);

    // 1) x -> f16
    conv_f16_kernel<<<(MTOT * DM) / (256 * 4), 256>>>(x, p_xf);
    // 2) transpose weights -> f16 [N,K]
    transpose_f16_kernel<<<dim3(3 * DM / 32, DM / 32), dim3(32, 8)>>>(w_qkv, p_wq, DM, 3 * DM);
    transpose_f16_kernel<<<dim3(DM / 32, DM / 32), dim3(32, 8)>>>(w_proj, p_wp, DM, DM);
    // 3) QKV projection (f16 HMMA) -> q/k bf16 hi/lo (q pre-scaled), v f16 hi/lo
    hmma_gemm<1><<<dim3(3 * DM / 128, MTOT / 128), 256, TS_TOTAL>>>(
        p_xf, p_wq, b_qkv, nullptr, 3 * DM, DM);
    // 4) causal flash attention (HMMA) -> g_af (f16)
    flash_hmma<<<dim3(SEQ / 128, BATCH * NH), 256, FS_TOTAL>>>();
    // 5) output projection (f16 HMMA) -> out
    hmma_gemm<2><<<dim3(DM / 128, MTOT / 128), 256, TS_TOTAL>>>(
        p_af, p_wp, b_proj, out, DM, DM);
}